// round 9
// baseline (speedup 1.0000x reference)
#include <cuda_runtime.h>
#include <cuda_fp16.h>
#include <math.h>
#include <cstdint>

#define BB 256
#define NN 256
#define DIN 128
#define DHH 128
#define HH 4
#define HD 512

// ---------------- scratch (device globals; no allocation allowed) ----------------
__device__ float g_y[(size_t)BB * NN * HD];         // [b][n][hd]
__device__ float g_hp[BB * NN];

// ===================== fused kernel smem layout (bytes) ======================
#define FS_ATT    0        // att_s[128] + att_d[128] fp32
#define FS_ASV    1024     // 256 f
#define FS_ADV    2048     // 256 f
#define FS_SKEY   3072     // 256 f
#define FS_JIDX   4096     // 256 i
#define FS_E1S    5120     // 256 f
#define FS_E2S    6144     // 256 f
#define FS_CS1    7168     // 257 f
#define FS_CS2    8256     // 257 f
#define FS_STMP   9344     // 16 f
#define FS_F1V    9472     // 256 f
#define FS_F2V    10496    // 256 f
#define FS_CKEY   11520    // 256 i
#define FS_STARTV 12544    // 18 i
#define FS_CP1    12672    // 17*128 f = 8704 B
#define FS_CP2    21376    // 8704 B
#define FS_HS     30720    // 256 x 136 halves = 69632 B (pitch 136 -> no bank conflicts)
#define FS_AHI    100352   // 32 KB fp16 A-frags (hi), 128 rows
#define FS_ALO    133120   // 32 KB (lo)
#define FS_WHI    165888   // 32 KB fp16 W-frags
#define FK_SMEM   198656
#define HS_PITCH  136

__device__ __forceinline__ void mma_f16(float* c, uint32_t a0, uint32_t a1, uint32_t a2,
                                        uint32_t a3, uint32_t b0, uint32_t b1) {
  asm volatile(
      "mma.sync.aligned.m16n8k16.row.col.f32.f16.f16.f32 "
      "{%0,%1,%2,%3}, {%4,%5,%6,%7}, {%8,%9}, {%0,%1,%2,%3};\n"
      : "+f"(c[0]), "+f"(c[1]), "+f"(c[2]), "+f"(c[3])
      : "r"(a0), "r"(a1), "r"(a2), "r"(a3), "r"(b0), "r"(b1));
}
__device__ __forceinline__ uint32_t pack_f16(float lo, float hi) {
  __half2 t(__float2half(lo), __float2half(hi));
  return *(uint32_t*)&t;
}

// ================= Fused: GEMM(head) + a_s/a_d + sorted-prefix softmax ========
// block = (b, h). GEMM 256x128 in two 128-row sub-phases (round-8 fragment code),
// h kept in smem fp16; then the chunked sorted-prefix aggregation on smem h.
__global__ __launch_bounds__(256, 1) void k_fused(
    const float* __restrict__ x, const float* __restrict__ W1,
    const float* __restrict__ att_src, const float* __restrict__ att_dst,
    const float* __restrict__ b1) {
  extern __shared__ char smem[];
  float* att = (float*)(smem + FS_ATT);
  float* asv = (float*)(smem + FS_ASV);
  float* adv = (float*)(smem + FS_ADV);
  __half* hs = (__half*)(smem + FS_HS);

  const int bh = blockIdx.x;
  const int h = bh & 3;
  const int b = bh >> 2;
  const int tid = threadIdx.x;
  const int wid = tid >> 5, lane = tid & 31;
  const int g = lane >> 2, tig = lane & 3;
  const int warp = wid;

  // att slices for this head
  if (tid < 128) att[tid] = att_src[(h << 7) + tid];
  else att[128 + (tid & 127)] = att_dst[(h << 7) + (tid & 127)];

  // ---- stage W (B = W1[:,h,:]^T) as fp16 fragments (resident for both halves) ----
  {
    char* whi = smem + FS_WHI;
    const int d = tid & 127;
    const int kbase = (tid >> 7) << 6;
    const int nt = d >> 3, wg = d & 7;
#pragma unroll 8
    for (int kk = 0; kk < 32; ++kk) {
      int k = kbase + (kk << 1);
      float w0 = __ldg(W1 + (size_t)(k * HH + h) * DHH + d);
      float w1 = __ldg(W1 + (size_t)((k + 1) * HH + h) * DHH + d);
      int ks = k >> 4;
      int kkm = k & 15;
      int btig = (kkm & 7) >> 1;
      int breg = (kkm >= 8) ? 1 : 0;
      int t = wg * 4 + btig;
      uint32_t byte = (uint32_t)(((ks * 16 + nt) * 32 + t) * 8 + breg * 4);
      *(uint32_t*)(whi + byte) = pack_f16(w0, w1);
    }
  }

  const float* att_s = att;
  const float* att_d = att + 128;

  for (int half = 0; half < 2; ++half) {
    const int hbase = half << 7;
    __syncthreads();  // W ready (first iter) / previous mainloop reads done

    // ---- stage A (x rows hbase..hbase+127) as hi/lo fp16 fragments ----
    {
      const float* xg = x + (size_t)(b * NN + hbase) * DIN;
      char* ahi = smem + FS_AHI;
      char* alo = smem + FS_ALO;
#pragma unroll
      for (int it = 0; it < 16; ++it) {
        int idx = it * 256 + tid;
        int row = idx >> 5;
        int k4 = (idx & 31) << 2;
        float4 v = *(const float4*)(xg + row * DIN + k4);
        float hx = __half2float(__float2half(v.x));
        float hy = __half2float(__float2half(v.y));
        float hz = __half2float(__float2half(v.z));
        float hw = __half2float(__float2half(v.w));
        uint32_t wh0 = pack_f16(hx, hy), wh1 = pack_f16(hz, hw);
        uint32_t wl0 = pack_f16(v.x - hx, v.y - hy), wl1 = pack_f16(v.z - hz, v.w - hw);
        int aw = row >> 4;
        int ag = row & 7;
        int areg = ((row & 15) >= 8 ? 1 : 0) + ((k4 & 15) >= 8 ? 2 : 0);
        int ks = k4 >> 4;
        int atig = (k4 & 7) >> 1;
        int t0 = ag * 4 + atig;
        uint32_t byte0 = (uint32_t)(((aw * 8 + ks) * 32 + t0) * 16 + areg * 4);
        uint32_t byte1 = (uint32_t)(((aw * 8 + ks) * 32 + t0 + 1) * 16 + areg * 4);
        *(uint32_t*)(ahi + byte0) = wh0;
        *(uint32_t*)(ahi + byte1) = wh1;
        *(uint32_t*)(alo + byte0) = wl0;
        *(uint32_t*)(alo + byte1) = wl1;
      }
    }
    __syncthreads();

    // ---- mma mainloop: 8 ksteps x 16 ntiles x 2 splits ----
    float acc[16][4];
#pragma unroll
    for (int nt = 0; nt < 16; ++nt)
#pragma unroll
      for (int q = 0; q < 4; ++q) acc[nt][q] = 0.f;

    const uint4* ahiF = (const uint4*)(smem + FS_AHI);
    const uint4* aloF = (const uint4*)(smem + FS_ALO);
    const uint2* whiF = (const uint2*)(smem + FS_WHI);

#pragma unroll
    for (int ks = 0; ks < 8; ++ks) {
      uint4 Ah = ahiF[(warp * 8 + ks) * 32 + lane];
      uint4 Al = aloF[(warp * 8 + ks) * 32 + lane];
#pragma unroll
      for (int nt = 0; nt < 16; ++nt) {
        uint2 Bh = whiF[(ks * 16 + nt) * 32 + lane];
        mma_f16(acc[nt], Ah.x, Ah.y, Ah.z, Ah.w, Bh.x, Bh.y);
        mma_f16(acc[nt], Al.x, Al.y, Al.z, Al.w, Bh.x, Bh.y);
      }
    }

    // ---- epilogue: att dots + fp16 h into smem ----
    const int r0 = warp << 4;
    float as0 = 0.f, as8 = 0.f, ad0 = 0.f, ad8 = 0.f;
    __half* hrow0 = hs + (hbase + r0 + g) * HS_PITCH;
    __half* hrow8 = hrow0 + 8 * HS_PITCH;
#pragma unroll
    for (int nt = 0; nt < 16; ++nt) {
      int c = (nt << 3) + (tig << 1);
      float s0 = att_s[c], s1 = att_s[c + 1];
      float d0 = att_d[c], d1 = att_d[c + 1];
      as0 = fmaf(acc[nt][0], s0, fmaf(acc[nt][1], s1, as0));
      ad0 = fmaf(acc[nt][0], d0, fmaf(acc[nt][1], d1, ad0));
      as8 = fmaf(acc[nt][2], s0, fmaf(acc[nt][3], s1, as8));
      ad8 = fmaf(acc[nt][2], d0, fmaf(acc[nt][3], d1, ad8));
      *(__half2*)(hrow0 + c) = __half2(__float2half(acc[nt][0]), __float2half(acc[nt][1]));
      *(__half2*)(hrow8 + c) = __half2(__float2half(acc[nt][2]), __float2half(acc[nt][3]));
    }
#pragma unroll
    for (int off = 1; off <= 2; off <<= 1) {
      as0 += __shfl_xor_sync(0xffffffffu, as0, off);
      ad0 += __shfl_xor_sync(0xffffffffu, ad0, off);
      as8 += __shfl_xor_sync(0xffffffffu, as8, off);
      ad8 += __shfl_xor_sync(0xffffffffu, ad8, off);
    }
    if (tig == 0) {
      asv[hbase + r0 + g] = as0;
      adv[hbase + r0 + g] = ad0;
      asv[hbase + r0 + g + 8] = as8;
      adv[hbase + r0 + g + 8] = ad8;
    }
  }
  __syncthreads();

  // ================= k2 phase on smem h =================
  float* skey = (float*)(smem + FS_SKEY);
  int* jidx = (int*)(smem + FS_JIDX);
  float* E1s = (float*)(smem + FS_E1S);
  float* E2s = (float*)(smem + FS_E2S);
  float* cS1 = (float*)(smem + FS_CS1);
  float* cS2 = (float*)(smem + FS_CS2);
  float* stmp = (float*)(smem + FS_STMP);
  float* F1v = (float*)(smem + FS_F1V);
  float* F2v = (float*)(smem + FS_F2V);
  int* ckey = (int*)(smem + FS_CKEY);
  int* startv = (int*)(smem + FS_STARTV);
  float* CP1 = (float*)(smem + FS_CP1);
  float* CP2 = (float*)(smem + FS_CP2);

  skey[tid] = asv[tid];
  jidx[tid] = tid;
  __syncthreads();

  // ---- bitonic sort #1: skey asc, carry jidx ----
#pragma unroll
  for (int size = 2; size <= NN; size <<= 1) {
#pragma unroll
    for (int stride = size >> 1; stride > 0; stride >>= 1) {
      int partner = tid ^ stride;
      if (partner > tid) {
        bool asc = ((tid & size) == 0);
        float k0 = skey[tid], k1 = skey[partner];
        if ((k0 > k1) == asc) {
          skey[tid] = k1; skey[partner] = k0;
          int j0 = jidx[tid], j1 = jidx[partner];
          jidx[tid] = j1; jidx[partner] = j0;
        }
      }
      __syncthreads();
    }
  }

  {
    float k = skey[tid];
    E1s[tid] = __expf(k);
    E2s[tid] = __expf(0.2f * k);
  }
  __syncthreads();

  // ---- scalar scans ----
  {
    float v1 = E1s[tid], v2 = E2s[tid];
#pragma unroll
    for (int off = 1; off < 32; off <<= 1) {
      float n1 = __shfl_up_sync(0xffffffffu, v1, off);
      float n2 = __shfl_up_sync(0xffffffffu, v2, off);
      if (lane >= off) { v1 += n1; v2 += n2; }
    }
    if (lane == 31) { stmp[wid] = v1; stmp[8 + wid] = v2; }
    __syncthreads();
    if (wid == 0 && lane < 8) {
      float w1 = stmp[lane], w2 = stmp[8 + lane];
#pragma unroll
      for (int off = 1; off < 8; off <<= 1) {
        float n1 = __shfl_up_sync(0xffu, w1, off);
        float n2 = __shfl_up_sync(0xffu, w2, off);
        if (lane >= off) { w1 += n1; w2 += n2; }
      }
      stmp[lane] = w1; stmp[8 + lane] = w2;
    }
    __syncthreads();
    float base1 = (wid > 0) ? stmp[wid - 1] : 0.f;
    float base2 = (wid > 0) ? stmp[8 + wid - 1] : 0.f;
    cS1[tid + 1] = v1 + base1;
    cS2[tid + 1] = v2 + base2;
    if (tid == 0) { cS1[0] = 0.f; cS2[0] = 0.f; }
  }
  __syncthreads();

  // ---- per-row scalars ----
  {
    const float ad = adv[tid];
    const float xneg = -ad;
    int lo = 0, hi = NN;
#pragma unroll
    for (int s = 0; s < 8; ++s) {
      int mid = (lo + hi) >> 1;
      if (skey[mid] > xneg) hi = mid; else lo = mid + 1;
    }
    int c = lo;
    float SP = cS1[NN] - cS1[c];
    float SN = cS2[c];
    float f1 = __expf(ad);
    float f2 = __expf(0.2f * ad);
    float r = 1.0f / (f1 * SP + f2 * SN);
    F1v[tid] = f1 * r;
    F2v[tid] = f2 * r;
    ckey[tid] = (c << 16) | tid;
  }
  __syncthreads();

  // ---- vector chunk checkpoints from smem h ----
  {
    const int d = tid & 127, halfg = tid >> 7;
#pragma unroll
    for (int cc = 0; cc < 8; ++cc) {
      const int c = halfg * 8 + cc;
      float s1 = 0.f, s2 = 0.f;
#pragma unroll
      for (int t = 0; t < 16; ++t) {
        int p = (c << 4) + t;
        int jp = jidx[p];
        float hv = __half2float(hs[jp * HS_PITCH + d]);
        s1 = fmaf(E1s[p], hv, s1);
        s2 = fmaf(E2s[p], hv, s2);
      }
      CP1[(c + 1) * 128 + d] = s1;
      CP2[(c + 1) * 128 + d] = s2;
    }
  }
  __syncthreads();
  if (tid < 128) {
    float run1 = 0.f, run2 = 0.f;
    CP1[tid] = 0.f; CP2[tid] = 0.f;
#pragma unroll
    for (int k = 1; k <= 16; ++k) {
      run1 += CP1[k * 128 + tid]; CP1[k * 128 + tid] = run1;
      run2 += CP2[k * 128 + tid]; CP2[k * 128 + tid] = run2;
    }
  }
  __syncthreads();

  // ---- bitonic sort #2: ckey asc ----
#pragma unroll
  for (int size = 2; size <= NN; size <<= 1) {
#pragma unroll
    for (int stride = size >> 1; stride > 0; stride >>= 1) {
      int partner = tid ^ stride;
      if (partner > tid) {
        bool asc = ((tid & size) == 0);
        int k0 = ckey[tid], k1 = ckey[partner];
        if ((k0 > k1) == asc) { ckey[tid] = k1; ckey[partner] = k0; }
      }
      __syncthreads();
    }
  }
  if (tid < 17) {
    int target = (tid * 16) << 16;
    int lo = 0, hi = NN;
    while (lo < hi) { int mid = (lo + hi) >> 1; if (ckey[mid] < target) lo = mid + 1; else hi = mid; }
    startv[tid] = lo;
  }
  if (tid == 17) startv[17] = NN;
  __syncthreads();

  // ---- emission straight from smem h ----
  const int tg = tid >> 7, d = tid & 127;
  const float bias_d = b1[(h << 7) + d];
  const float T1d = CP1[(16 << 7) + d];
  float* yb = g_y + (size_t)b * NN * HD + (h << 7) + d;

  for (int ch = 0; ch < 16; ++ch) {
    const int lo = startv[ch], hi = startv[ch + 1];
    const float P1b = CP1[(ch << 7) + d], P2b = CP2[(ch << 7) + d];
    for (int r = lo + tg; r < hi; r += 2) {
      int ck = ckey[r];
      int i = ck & 0xffff;
      int c = ck >> 16;
      float P1 = P1b, P2 = P2b;
#pragma unroll 4
      for (int p = ch << 4; p < c; ++p) {
        float hv = __half2float(hs[jidx[p] * HS_PITCH + d]);
        P1 = fmaf(E1s[p], hv, P1);
        P2 = fmaf(E2s[p], hv, P2);
      }
      yb[(size_t)i * HD] = fmaf(F1v[i], T1d - P1, F2v[i] * P2) + bias_d;
    }
  }
  {
    const float P2t = CP2[(16 << 7) + d];
    for (int r = startv[16] + tg; r < NN; r += 2) {
      int i = ckey[r] & 0xffff;
      yb[(size_t)i * HD] = F2v[i] * P2t + bias_d;
    }
  }
}

// ================= Kernel 3: LayerNorm + ELU + projection -> hp ===============
__global__ __launch_bounds__(256) void k3_ln(
    const float* __restrict__ gamma, const float* __restrict__ beta,
    const float* __restrict__ W2) {
  const int w = threadIdx.x >> 5, lane = threadIdx.x & 31;
  const int row = blockIdx.x * 8 + w;
  const float* yr = g_y + (size_t)row * HD;
  float4 v[4];
  float s = 0.f, sq = 0.f;
#pragma unroll
  for (int k = 0; k < 4; ++k) {
    v[k] = *(const float4*)(yr + (((k << 5) + lane) << 2));
    s += v[k].x + v[k].y + v[k].z + v[k].w;
    sq += v[k].x * v[k].x + v[k].y * v[k].y + v[k].z * v[k].z + v[k].w * v[k].w;
  }
#pragma unroll
  for (int off = 16; off > 0; off >>= 1) {
    s += __shfl_xor_sync(0xffffffffu, s, off);
    sq += __shfl_xor_sync(0xffffffffu, sq, off);
  }
  const float mu = s * (1.0f / 512.0f);
  const float var = sq * (1.0f / 512.0f) - mu * mu;
  const float rinv = rsqrtf(var + 1e-5f);
  float hp = 0.f;
#pragma unroll
  for (int k = 0; k < 4; ++k) {
    int c = (((k << 5) + lane) << 2);
    float4 g4 = *(const float4*)(gamma + c);
    float4 b4 = *(const float4*)(beta + c);
    float4 w4 = *(const float4*)(W2 + c);
    float t, e;
    t = (v[k].x - mu) * rinv * g4.x + b4.x; e = t > 0.f ? t : expm1f(t); hp = fmaf(e, w4.x, hp);
    t = (v[k].y - mu) * rinv * g4.y + b4.y; e = t > 0.f ? t : expm1f(t); hp = fmaf(e, w4.y, hp);
    t = (v[k].z - mu) * rinv * g4.z + b4.z; e = t > 0.f ? t : expm1f(t); hp = fmaf(e, w4.z, hp);
    t = (v[k].w - mu) * rinv * g4.w + b4.w; e = t > 0.f ? t : expm1f(t); hp = fmaf(e, w4.w, hp);
  }
#pragma unroll
  for (int off = 16; off > 0; off >>= 1) hp += __shfl_xor_sync(0xffffffffu, hp, off);
  if (lane == 0) g_hp[row] = hp;
}

// ================= Kernel 4: layer-2 scalar attention per batch ===============
__global__ __launch_bounds__(256) void k4_attn2(
    const float* __restrict__ att_src2, const float* __restrict__ att_dst2,
    const float* __restrict__ b2, float* __restrict__ out) {
  __shared__ float asv[NN], E1[NN], E2[NN], P1[NN], P2[NN];
  const int b = blockIdx.x, tid = threadIdx.x;
  const float v = g_hp[b * NN + tid];
  const float a_src = att_src2[0], a_dst = att_dst2[0];
  const float as = v * a_src;
  asv[tid] = as;
  const float e1 = __expf(as), e2 = __expf(0.2f * as);
  E1[tid] = e1; E2[tid] = e2; P1[tid] = e1 * v; P2[tid] = e2 * v;
  __syncthreads();
  const float ad = v * a_dst;
  float SP = 0.f, SN = 0.f, NP = 0.f, NNa = 0.f;
#pragma unroll 4
  for (int j = 0; j < NN; ++j) {
    float t = ad + asv[j];
    if (t > 0.f) { SP += E1[j]; NP += P1[j]; }
    else         { SN += E2[j]; NNa += P2[j]; }
  }
  const float f1 = __expf(ad), f2 = __expf(0.2f * ad);
  out[b * NN + tid] = (f1 * NP + f2 * NNa) / (f1 * SP + f2 * SN) + b2[0];
}

// ================================ launch ======================================
extern "C" void kernel_launch(void* const* d_in, const int* in_sizes, int n_in,
                              void* d_out, int out_size) {
  const float* x    = (const float*)d_in[0];
  const float* W1   = (const float*)d_in[2];
  const float* as1  = (const float*)d_in[3];
  const float* ad1  = (const float*)d_in[4];
  const float* b1   = (const float*)d_in[5];
  const float* gam  = (const float*)d_in[6];
  const float* bet  = (const float*)d_in[7];
  const float* W2   = (const float*)d_in[8];
  const float* as2  = (const float*)d_in[9];
  const float* ad2  = (const float*)d_in[10];
  const float* b2   = (const float*)d_in[11];
  float* out = (float*)d_out;

  cudaFuncSetAttribute(k_fused, cudaFuncAttributeMaxDynamicSharedMemorySize, FK_SMEM);

  k_fused<<<BB * HH, 256, FK_SMEM>>>(x, W1, as1, ad1, b1);
  k3_ln<<<BB * NN / 8, 256>>>(gam, bet, W2);
  k4_attn2<<<BB, 256>>>(as2, ad2, b2, out);
}

// round 10
// speedup vs baseline: 1.2861x; 1.2861x over previous
#include <cuda_runtime.h>
#include <cuda_fp16.h>
#include <math.h>
#include <cstdint>

#define BB 256
#define NN 256
#define DIN 128
#define DHH 128
#define HH 4
#define HD 512

// ---------------- scratch (device globals; no allocation allowed) ----------------
__device__ __half g_h[(size_t)BB * HH * NN * DHH];  // [b][h][j][d] fp16, 67 MB
__device__ float g_as[BB * HH * NN];                // [b][h][n]
__device__ float g_ad[BB * HH * NN];
__device__ float g_y[(size_t)BB * NN * HD];         // [b][n][hd]
__device__ float g_hp[BB * NN];

// ================= Kernel 1 (mma.sync fp16x2): h = x @ W1 + a_s/a_d ==========
#define SM_ATT 0                       // att_src[512] + att_dst[512] fp32
#define SM_AHI 4096
#define SM_ALO (SM_AHI + 32768)
#define SM_WHI (SM_ALO + 32768)
#define K1_SMEM (SM_WHI + 32768)

__device__ __forceinline__ void mma_f16(float* c, uint32_t a0, uint32_t a1, uint32_t a2,
                                        uint32_t a3, uint32_t b0, uint32_t b1) {
  asm volatile(
      "mma.sync.aligned.m16n8k16.row.col.f32.f16.f16.f32 "
      "{%0,%1,%2,%3}, {%4,%5,%6,%7}, {%8,%9}, {%0,%1,%2,%3};\n"
      : "+f"(c[0]), "+f"(c[1]), "+f"(c[2]), "+f"(c[3])
      : "r"(a0), "r"(a1), "r"(a2), "r"(a3), "r"(b0), "r"(b1));
}
__device__ __forceinline__ uint32_t pack_f16(float lo, float hi) {
  __half2 t(__float2half(lo), __float2half(hi));
  return *(uint32_t*)&t;
}

__global__ __launch_bounds__(256, 2) void k1_mma(
    const float* __restrict__ x, const float* __restrict__ W1,
    const float* __restrict__ att_src, const float* __restrict__ att_dst) {
  extern __shared__ char smem[];
  float* att = (float*)(smem + SM_ATT);
  const int tid = threadIdx.x;
  const int wid = tid >> 5, lane = tid & 31;
  const int g = lane >> 2, tig = lane & 3;
  const int bx = blockIdx.x;
  const int b = bx >> 1;
  const int n0 = (bx & 1) << 7;

  {
    att[tid] = att_src[tid];
    att[256 + tid] = att_src[256 + tid];
    att[512 + tid] = att_dst[tid];
    att[768 + tid] = att_dst[256 + tid];
  }

  // ---- stage A (x rows n0..n0+127) as hi/lo fp16 fragments ----
  {
    const float* xg = x + (size_t)(b * NN + n0) * DIN;
    char* ahi = smem + SM_AHI;
    char* alo = smem + SM_ALO;
#pragma unroll
    for (int it = 0; it < 16; ++it) {
      int idx = it * 256 + tid;
      int row = idx >> 5;
      int k4 = (idx & 31) << 2;
      float4 v = *(const float4*)(xg + row * DIN + k4);
      float hx = __half2float(__float2half(v.x));
      float hy = __half2float(__float2half(v.y));
      float hz = __half2float(__float2half(v.z));
      float hw = __half2float(__float2half(v.w));
      uint32_t wh0 = pack_f16(hx, hy), wh1 = pack_f16(hz, hw);
      uint32_t wl0 = pack_f16(v.x - hx, v.y - hy), wl1 = pack_f16(v.z - hz, v.w - hw);
      int aw = row >> 4;
      int ag = row & 7;
      int areg = ((row & 15) >= 8 ? 1 : 0) + ((k4 & 15) >= 8 ? 2 : 0);
      int ks = k4 >> 4;
      int atig = (k4 & 7) >> 1;
      int t0 = ag * 4 + atig;
      uint32_t byte0 = (uint32_t)(((aw * 8 + ks) * 32 + t0) * 16 + areg * 4);
      uint32_t byte1 = (uint32_t)(((aw * 8 + ks) * 32 + t0 + 1) * 16 + areg * 4);
      *(uint32_t*)(ahi + byte0) = wh0;
      *(uint32_t*)(ahi + byte1) = wh1;
      *(uint32_t*)(alo + byte0) = wl0;
      *(uint32_t*)(alo + byte1) = wl1;
    }
  }

  const float* att_s = att;
  const float* att_d = att + 512;
  const int r0 = wid << 4;

  for (int ch = 0; ch < HH; ++ch) {
    __syncthreads();
    // ---- stage W chunk as fp16 fragments ----
    {
      char* whi = smem + SM_WHI;
      const int d = tid & 127;
      const int kbase = (tid >> 7) << 6;
      const int nt = d >> 3, wg = d & 7;
#pragma unroll 8
      for (int kk = 0; kk < 32; ++kk) {
        int k = kbase + (kk << 1);
        float w0 = __ldg(W1 + (size_t)(k * HH + ch) * DHH + d);
        float w1 = __ldg(W1 + (size_t)((k + 1) * HH + ch) * DHH + d);
        int ks = k >> 4;
        int kkm = k & 15;
        int btig = (kkm & 7) >> 1;
        int breg = (kkm >= 8) ? 1 : 0;
        int t = wg * 4 + btig;
        uint32_t byte = (uint32_t)(((ks * 16 + nt) * 32 + t) * 8 + breg * 4);
        *(uint32_t*)(whi + byte) = pack_f16(w0, w1);
      }
    }
    __syncthreads();

    float acc[16][4];
#pragma unroll
    for (int nt = 0; nt < 16; ++nt)
#pragma unroll
      for (int q = 0; q < 4; ++q) acc[nt][q] = 0.f;

    const uint4* ahiF = (const uint4*)(smem + SM_AHI);
    const uint4* aloF = (const uint4*)(smem + SM_ALO);
    const uint2* whiF = (const uint2*)(smem + SM_WHI);

#pragma unroll
    for (int ks = 0; ks < 8; ++ks) {
      uint4 Ah = ahiF[(wid * 8 + ks) * 32 + lane];
      uint4 Al = aloF[(wid * 8 + ks) * 32 + lane];
#pragma unroll
      for (int nt = 0; nt < 16; ++nt) {
        uint2 Bh = whiF[(ks * 16 + nt) * 32 + lane];
        mma_f16(acc[nt], Ah.x, Ah.y, Ah.z, Ah.w, Bh.x, Bh.y);
        mma_f16(acc[nt], Al.x, Al.y, Al.z, Al.w, Bh.x, Bh.y);
      }
    }

    // ---- epilogue: att dots + fp16 h stores ----
    float as0 = 0.f, as8 = 0.f, ad0 = 0.f, ad8 = 0.f;
    __half* hrow0 = g_h + (size_t)((b * HH + ch) * NN + n0 + r0 + g) * DHH;
    __half* hrow8 = hrow0 + (size_t)8 * DHH;
#pragma unroll
    for (int nt = 0; nt < 16; ++nt) {
      int c = (nt << 3) + (tig << 1);
      float s0 = att_s[(ch << 7) + c], s1 = att_s[(ch << 7) + c + 1];
      float d0 = att_d[(ch << 7) + c], d1 = att_d[(ch << 7) + c + 1];
      as0 = fmaf(acc[nt][0], s0, fmaf(acc[nt][1], s1, as0));
      ad0 = fmaf(acc[nt][0], d0, fmaf(acc[nt][1], d1, ad0));
      as8 = fmaf(acc[nt][2], s0, fmaf(acc[nt][3], s1, as8));
      ad8 = fmaf(acc[nt][2], d0, fmaf(acc[nt][3], d1, ad8));
      *(__half2*)(hrow0 + c) = __half2(__float2half(acc[nt][0]), __float2half(acc[nt][1]));
      *(__half2*)(hrow8 + c) = __half2(__float2half(acc[nt][2]), __float2half(acc[nt][3]));
    }
#pragma unroll
    for (int off = 1; off <= 2; off <<= 1) {
      as0 += __shfl_xor_sync(0xffffffffu, as0, off);
      ad0 += __shfl_xor_sync(0xffffffffu, ad0, off);
      as8 += __shfl_xor_sync(0xffffffffu, as8, off);
      ad8 += __shfl_xor_sync(0xffffffffu, ad8, off);
    }
    if (tig == 0) {
      size_t base = (size_t)(b * HH + ch) * NN + n0 + r0 + g;
      g_as[base] = as0;
      g_ad[base] = ad0;
      g_as[base + 8] = as8;
      g_ad[base + 8] = ad8;
    }
  }
}

// ================= Kernel 2 v4: chunked sorted-prefix + fp16 h + cp.async ======
__device__ __forceinline__ uint32_t smem_u32_k2(const void* p) {
  uint32_t a;
  asm("{ .reg .u64 t; cvta.to.shared.u64 t, %1; cvt.u32.u64 %0, t; }" : "=r"(a) : "l"(p));
  return a;
}
__device__ __forceinline__ void cp16(uint32_t dst, const void* src) {
  asm volatile("cp.async.cg.shared.global [%0], [%1], 16;" :: "r"(dst), "l"(src) : "memory");
}
#define CP_COMMIT() asm volatile("cp.async.commit_group;" ::: "memory")
#define CP_WAIT(n)  asm volatile("cp.async.wait_group %0;" :: "n"(n) : "memory")

__global__ __launch_bounds__(256, 4) void k2_sweep(const float* __restrict__ b1) {
  __shared__ float skey[NN];
  __shared__ int   jidx[NN];
  __shared__ float E1s[NN], E2s[NN];
  __shared__ float cS1[NN + 1], cS2[NN + 1];
  __shared__ float stmp[16];
  __shared__ float F1v[NN], F2v[NN];
  __shared__ int   ckey[NN];
  __shared__ int   startv[18];
  __shared__ float CP1[17 * 128], CP2[17 * 128];
  __shared__ __half hbuf[2][16 * 128];   // fp16, 8 KB total

  const int bh = blockIdx.x;
  const int h = bh & 3;
  const int b = bh >> 2;
  const int tid = threadIdx.x;
  const int lane = tid & 31, warp = tid >> 5;
  const __half* hb = g_h + (size_t)bh * NN * DHH;
  const uint32_t hbuf_addr = smem_u32_k2(hbuf);

  skey[tid] = g_as[bh * NN + tid];
  jidx[tid] = tid;
  __syncthreads();

#pragma unroll
  for (int size = 2; size <= NN; size <<= 1) {
#pragma unroll
    for (int stride = size >> 1; stride > 0; stride >>= 1) {
      int partner = tid ^ stride;
      if (partner > tid) {
        bool asc = ((tid & size) == 0);
        float k0 = skey[tid], k1 = skey[partner];
        if ((k0 > k1) == asc) {
          skey[tid] = k1; skey[partner] = k0;
          int j0 = jidx[tid], j1 = jidx[partner];
          jidx[tid] = j1; jidx[partner] = j0;
        }
      }
      __syncthreads();
    }
  }

  {
    float k = skey[tid];
    E1s[tid] = __expf(k);
    E2s[tid] = __expf(0.2f * k);
  }
  __syncthreads();

  {
    float v1 = E1s[tid], v2 = E2s[tid];
#pragma unroll
    for (int off = 1; off < 32; off <<= 1) {
      float n1 = __shfl_up_sync(0xffffffffu, v1, off);
      float n2 = __shfl_up_sync(0xffffffffu, v2, off);
      if (lane >= off) { v1 += n1; v2 += n2; }
    }
    if (lane == 31) { stmp[warp] = v1; stmp[8 + warp] = v2; }
    __syncthreads();
    if (warp == 0 && lane < 8) {
      float w1 = stmp[lane], w2 = stmp[8 + lane];
#pragma unroll
      for (int off = 1; off < 8; off <<= 1) {
        float n1 = __shfl_up_sync(0xffu, w1, off);
        float n2 = __shfl_up_sync(0xffu, w2, off);
        if (lane >= off) { w1 += n1; w2 += n2; }
      }
      stmp[lane] = w1; stmp[8 + lane] = w2;
    }
    __syncthreads();
    float base1 = (warp > 0) ? stmp[warp - 1] : 0.f;
    float base2 = (warp > 0) ? stmp[8 + warp - 1] : 0.f;
    cS1[tid + 1] = v1 + base1;
    cS2[tid + 1] = v2 + base2;
    if (tid == 0) { cS1[0] = 0.f; cS2[0] = 0.f; }
  }
  __syncthreads();

  {
    const float ad = g_ad[bh * NN + tid];
    const float xneg = -ad;
    int lo = 0, hi = NN;
#pragma unroll
    for (int s = 0; s < 8; ++s) {
      int mid = (lo + hi) >> 1;
      if (skey[mid] > xneg) hi = mid; else lo = mid + 1;
    }
    int c = lo;
    float SP = cS1[NN] - cS1[c];
    float SN = cS2[c];
    float f1 = __expf(ad);
    float f2 = __expf(0.2f * ad);
    float r = 1.0f / (f1 * SP + f2 * SN);
    F1v[tid] = f1 * r;
    F2v[tid] = f2 * r;
    ckey[tid] = (c << 16) | tid;
  }
  __syncthreads();

  // ---- vector chunk checkpoints (fp16 reads) ----
  {
    const int d = tid & 127, half = tid >> 7;
#pragma unroll
    for (int cc = 0; cc < 8; ++cc) {
      const int c = half * 8 + cc;
      float s1 = 0.f, s2 = 0.f;
#pragma unroll
      for (int t = 0; t < 16; ++t) {
        int p = (c << 4) + t;
        int jp = jidx[p];
        float hv = __half2float(__ldg(hb + (size_t)jp * DHH + d));
        s1 = fmaf(E1s[p], hv, s1);
        s2 = fmaf(E2s[p], hv, s2);
      }
      CP1[(c + 1) * 128 + d] = s1;
      CP2[(c + 1) * 128 + d] = s2;
    }
  }

  // prefetch chunk 0 (16 rows x 256B = 256 x 16B cps)
  {
    int t = tid >> 4, d8 = tid & 15;
    int jp = jidx[t];
    cp16(hbuf_addr + (uint32_t)tid * 16u, hb + (size_t)jp * DHH + d8 * 8);
    CP_COMMIT();
  }

  __syncthreads();
  if (tid < 128) {
    float run1 = 0.f, run2 = 0.f;
    CP1[tid] = 0.f; CP2[tid] = 0.f;
#pragma unroll
    for (int k = 1; k <= 16; ++k) {
      run1 += CP1[k * 128 + tid]; CP1[k * 128 + tid] = run1;
      run2 += CP2[k * 128 + tid]; CP2[k * 128 + tid] = run2;
    }
  }
  __syncthreads();

#pragma unroll
  for (int size = 2; size <= NN; size <<= 1) {
#pragma unroll
    for (int stride = size >> 1; stride > 0; stride >>= 1) {
      int partner = tid ^ stride;
      if (partner > tid) {
        bool asc = ((tid & size) == 0);
        int k0 = ckey[tid], k1 = ckey[partner];
        if ((k0 > k1) == asc) { ckey[tid] = k1; ckey[partner] = k0; }
      }
      __syncthreads();
    }
  }
  if (tid < 17) {
    int target = (tid * 16) << 16;
    int lo = 0, hi = NN;
    while (lo < hi) { int mid = (lo + hi) >> 1; if (ckey[mid] < target) lo = mid + 1; else hi = mid; }
    startv[tid] = lo;
  }
  if (tid == 17) startv[17] = NN;
  __syncthreads();

  // ---- emission: 16 double-buffered phases + exact tail ----
  const int tg = tid >> 7, d = tid & 127;
  const float bias_d = b1[(h << 7) + d];
  const float T1d = CP1[(16 << 7) + d];
  float* yb = g_y + (size_t)b * NN * HD + (h << 7) + d;

  for (int ch = 0; ch < 16; ++ch) {
    if (ch < 15) {
      uint32_t hdst = hbuf_addr + (uint32_t)(((ch + 1) & 1) * 4096);
      int t = tid >> 4, d8 = tid & 15;
      int jp = jidx[((ch + 1) << 4) + t];
      cp16(hdst + (uint32_t)tid * 16u, hb + (size_t)jp * DHH + d8 * 8);
      CP_COMMIT();
      CP_WAIT(1);
    } else {
      CP_WAIT(0);
    }
    __syncthreads();

    const __half* hs = hbuf[ch & 1];
    const int lo = startv[ch], hi = startv[ch + 1];
    const float P1b = CP1[(ch << 7) + d], P2b = CP2[(ch << 7) + d];
    for (int r = lo + tg; r < hi; r += 2) {
      int ck = ckey[r];
      int i = ck & 0xffff;
      int c = ck >> 16;
      float P1 = P1b, P2 = P2b;
#pragma unroll 4
      for (int p = ch << 4; p < c; ++p) {
        float hv = __half2float(hs[((p - (ch << 4)) << 7) + d]);
        P1 = fmaf(E1s[p], hv, P1);
        P2 = fmaf(E2s[p], hv, P2);
      }
      yb[(size_t)i * HD] = fmaf(F1v[i], T1d - P1, F2v[i] * P2) + bias_d;
    }
    __syncthreads();
  }
  {
    const float P2t = CP2[(16 << 7) + d];
    for (int r = startv[16] + tg; r < NN; r += 2) {
      int i = ckey[r] & 0xffff;
      yb[(size_t)i * HD] = F2v[i] * P2t + bias_d;
    }
  }
}

// ================= Kernel 3+4 merged: LN + ELU + proj + layer-2 attention =====
__global__ __launch_bounds__(256) void k34(
    const float* __restrict__ gamma, const float* __restrict__ beta,
    const float* __restrict__ W2,
    const float* __restrict__ att_src2, const float* __restrict__ att_dst2,
    const float* __restrict__ b2, float* __restrict__ out) {
  __shared__ float hp[NN], asv[NN], E1[NN], E2[NN], P1s[NN], P2s[NN];
  const int b = blockIdx.x, tid = threadIdx.x;
  const int w = tid >> 5, lane = tid & 31;

  // LN + ELU + projection for rows w, w+8, ..., w+248
  for (int r = w; r < NN; r += 8) {
    const float* yr = g_y + ((size_t)b * NN + r) * HD;
    float4 v[4];
    float s = 0.f, sq = 0.f;
#pragma unroll
    for (int k = 0; k < 4; ++k) {
      v[k] = *(const float4*)(yr + (((k << 5) + lane) << 2));
      s += v[k].x + v[k].y + v[k].z + v[k].w;
      sq += v[k].x * v[k].x + v[k].y * v[k].y + v[k].z * v[k].z + v[k].w * v[k].w;
    }
#pragma unroll
    for (int off = 16; off > 0; off >>= 1) {
      s += __shfl_xor_sync(0xffffffffu, s, off);
      sq += __shfl_xor_sync(0xffffffffu, sq, off);
    }
    const float mu = s * (1.0f / 512.0f);
    const float var = sq * (1.0f / 512.0f) - mu * mu;
    const float rinv = rsqrtf(var + 1e-5f);
    float acc = 0.f;
#pragma unroll
    for (int k = 0; k < 4; ++k) {
      int c = (((k << 5) + lane) << 2);
      float4 g4 = *(const float4*)(gamma + c);
      float4 b4 = *(const float4*)(beta + c);
      float4 w4 = *(const float4*)(W2 + c);
      float t, e;
      t = (v[k].x - mu) * rinv * g4.x + b4.x; e = t > 0.f ? t : expm1f(t); acc = fmaf(e, w4.x, acc);
      t = (v[k].y - mu) * rinv * g4.y + b4.y; e = t > 0.f ? t : expm1f(t); acc = fmaf(e, w4.y, acc);
      t = (v[k].z - mu) * rinv * g4.z + b4.z; e = t > 0.f ? t : expm1f(t); acc = fmaf(e, w4.z, acc);
      t = (v[k].w - mu) * rinv * g4.w + b4.w; e = t > 0.f ? t : expm1f(t); acc = fmaf(e, w4.w, acc);
    }
#pragma unroll
    for (int off = 16; off > 0; off >>= 1) acc += __shfl_xor_sync(0xffffffffu, acc, off);
    if (lane == 0) hp[r] = acc;
  }
  __syncthreads();

  // layer-2 scalar attention
  const float v = hp[tid];
  const float a_src = att_src2[0], a_dst = att_dst2[0];
  const float as = v * a_src;
  asv[tid] = as;
  const float e1 = __expf(as), e2 = __expf(0.2f * as);
  E1[tid] = e1; E2[tid] = e2; P1s[tid] = e1 * v; P2s[tid] = e2 * v;
  __syncthreads();
  const float ad = v * a_dst;
  float SP = 0.f, SN = 0.f, NP = 0.f, NNa = 0.f;
#pragma unroll 4
  for (int j = 0; j < NN; ++j) {
    float t = ad + asv[j];
    if (t > 0.f) { SP += E1[j]; NP += P1s[j]; }
    else         { SN += E2[j]; NNa += P2s[j]; }
  }
  const float f1 = __expf(ad), f2 = __expf(0.2f * ad);
  out[b * NN + tid] = (f1 * NP + f2 * NNa) / (f1 * SP + f2 * SN) + b2[0];
}

// ================================ launch ======================================
extern "C" void kernel_launch(void* const* d_in, const int* in_sizes, int n_in,
                              void* d_out, int out_size) {
  const float* x    = (const float*)d_in[0];
  const float* W1   = (const float*)d_in[2];
  const float* as1  = (const float*)d_in[3];
  const float* ad1  = (const float*)d_in[4];
  const float* b1   = (const float*)d_in[5];
  const float* gam  = (const float*)d_in[6];
  const float* bet  = (const float*)d_in[7];
  const float* W2   = (const float*)d_in[8];
  const float* as2  = (const float*)d_in[9];
  const float* ad2  = (const float*)d_in[10];
  const float* b2   = (const float*)d_in[11];
  float* out = (float*)d_out;

  cudaFuncSetAttribute(k1_mma, cudaFuncAttributeMaxDynamicSharedMemorySize, K1_SMEM);

  k1_mma<<<512, 256, K1_SMEM>>>(x, W1, as1, ad1);
  k2_sweep<<<BB * HH, 256>>>(b1);
  k34<<<BB, 256>>>(gam, bet, W2, as2, ad2, b2, out);
}

// round 12
// speedup vs baseline: 1.6009x; 1.2448x over previous
#include <cuda_runtime.h>
#include <cuda_fp16.h>
#include <math.h>
#include <cstdint>

#define BB 256
#define NN 256
#define DIN 128
#define DHH 128
#define HH 4
#define HD 512

// ---------------- scratch (device globals; no allocation allowed) ----------------
__device__ __half g_h[(size_t)BB * HH * NN * DHH];  // [b][h][j][d] fp16
__device__ float g_as[BB * HH * NN];
__device__ float g_ad[BB * HH * NN];
__device__ float g_y[(size_t)BB * NN * HD];         // [b][n][hd]
__device__ float g_hp[BB * NN];

// ===================== common helpers =====================
__device__ __forceinline__ void mma_f16(float* c, uint32_t a0, uint32_t a1, uint32_t a2,
                                        uint32_t a3, uint32_t b0, uint32_t b1) {
  asm volatile(
      "mma.sync.aligned.m16n8k16.row.col.f32.f16.f16.f32 "
      "{%0,%1,%2,%3}, {%4,%5,%6,%7}, {%8,%9}, {%0,%1,%2,%3};\n"
      : "+f"(c[0]), "+f"(c[1]), "+f"(c[2]), "+f"(c[3])
      : "r"(a0), "r"(a1), "r"(a2), "r"(a3), "r"(b0), "r"(b1));
}
__device__ __forceinline__ uint32_t pack_f16(float lo, float hi) {
  __half2 t(__float2half(lo), __float2half(hi));
  return *(uint32_t*)&t;
}
__device__ __forceinline__ uint32_t smem_u32g(const void* p) {
  uint32_t a;
  asm("{ .reg .u64 t; cvta.to.shared.u64 t, %1; cvt.u32.u64 %0, t; }" : "=r"(a) : "l"(p));
  return a;
}
__device__ __forceinline__ void cp16(uint32_t dst, const void* src) {
  asm volatile("cp.async.cg.shared.global [%0], [%1], 16;" :: "r"(dst), "l"(src) : "memory");
}
#define CP_COMMIT() asm volatile("cp.async.commit_group;" ::: "memory")
#define CP_WAIT(n)  asm volatile("cp.async.wait_group %0;" :: "n"(n) : "memory")
__device__ __forceinline__ void ldm_x4t(uint32_t& r0, uint32_t& r1, uint32_t& r2, uint32_t& r3,
                                        uint32_t addr) {
  asm volatile("ldmatrix.sync.aligned.m8n8.x4.trans.shared.b16 {%0,%1,%2,%3}, [%4];"
               : "=r"(r0), "=r"(r1), "=r"(r2), "=r"(r3) : "r"(addr));
}

// ================= Kernel 1 (mma.sync fp16x2): h = x @ W1 + a_s/a_d ==========
#define SM_ATT 0
#define SM_AHI 4096
#define SM_ALO (SM_AHI + 32768)
#define SM_WHI (SM_ALO + 32768)
#define K1_SMEM (SM_WHI + 32768)

__global__ __launch_bounds__(256, 2) void k1_mma(
    const float* __restrict__ x, const float* __restrict__ W1,
    const float* __restrict__ att_src, const float* __restrict__ att_dst) {
  extern __shared__ char smem[];
  float* att = (float*)(smem + SM_ATT);
  const int tid = threadIdx.x;
  const int wid = tid >> 5, lane = tid & 31;
  const int g = lane >> 2, tig = lane & 3;
  const int bx = blockIdx.x;
  const int b = bx >> 1;
  const int n0 = (bx & 1) << 7;

  {
    att[tid] = att_src[tid];
    att[256 + tid] = att_src[256 + tid];
    att[512 + tid] = att_dst[tid];
    att[768 + tid] = att_dst[256 + tid];
  }

  {
    const float* xg = x + (size_t)(b * NN + n0) * DIN;
    char* ahi = smem + SM_AHI;
    char* alo = smem + SM_ALO;
#pragma unroll
    for (int it = 0; it < 16; ++it) {
      int idx = it * 256 + tid;
      int row = idx >> 5;
      int k4 = (idx & 31) << 2;
      float4 v = *(const float4*)(xg + row * DIN + k4);
      float hx = __half2float(__float2half(v.x));
      float hy = __half2float(__float2half(v.y));
      float hz = __half2float(__float2half(v.z));
      float hw = __half2float(__float2half(v.w));
      uint32_t wh0 = pack_f16(hx, hy), wh1 = pack_f16(hz, hw);
      uint32_t wl0 = pack_f16(v.x - hx, v.y - hy), wl1 = pack_f16(v.z - hz, v.w - hw);
      int aw = row >> 4;
      int ag = row & 7;
      int areg = ((row & 15) >= 8 ? 1 : 0) + ((k4 & 15) >= 8 ? 2 : 0);
      int ks = k4 >> 4;
      int atig = (k4 & 7) >> 1;
      int t0 = ag * 4 + atig;
      uint32_t byte0 = (uint32_t)(((aw * 8 + ks) * 32 + t0) * 16 + areg * 4);
      uint32_t byte1 = (uint32_t)(((aw * 8 + ks) * 32 + t0 + 1) * 16 + areg * 4);
      *(uint32_t*)(ahi + byte0) = wh0;
      *(uint32_t*)(ahi + byte1) = wh1;
      *(uint32_t*)(alo + byte0) = wl0;
      *(uint32_t*)(alo + byte1) = wl1;
    }
  }

  const float* att_s = att;
  const float* att_d = att + 512;
  const int r0 = wid << 4;

  for (int ch = 0; ch < HH; ++ch) {
    __syncthreads();
    {
      char* whi = smem + SM_WHI;
      const int d = tid & 127;
      const int kbase = (tid >> 7) << 6;
      const int nt = d >> 3, wg = d & 7;
#pragma unroll 8
      for (int kk = 0; kk < 32; ++kk) {
        int k = kbase + (kk << 1);
        float w0 = __ldg(W1 + (size_t)(k * HH + ch) * DHH + d);
        float w1 = __ldg(W1 + (size_t)((k + 1) * HH + ch) * DHH + d);
        int ks = k >> 4;
        int kkm = k & 15;
        int btig = (kkm & 7) >> 1;
        int breg = (kkm >= 8) ? 1 : 0;
        int t = wg * 4 + btig;
        uint32_t byte = (uint32_t)(((ks * 16 + nt) * 32 + t) * 8 + breg * 4);
        *(uint32_t*)(whi + byte) = pack_f16(w0, w1);
      }
    }
    __syncthreads();

    float acc[16][4];
#pragma unroll
    for (int nt = 0; nt < 16; ++nt)
#pragma unroll
      for (int q = 0; q < 4; ++q) acc[nt][q] = 0.f;

    const uint4* ahiF = (const uint4*)(smem + SM_AHI);
    const uint4* aloF = (const uint4*)(smem + SM_ALO);
    const uint2* whiF = (const uint2*)(smem + SM_WHI);

#pragma unroll
    for (int ks = 0; ks < 8; ++ks) {
      uint4 Ah = ahiF[(wid * 8 + ks) * 32 + lane];
      uint4 Al = aloF[(wid * 8 + ks) * 32 + lane];
#pragma unroll
      for (int nt = 0; nt < 16; ++nt) {
        uint2 Bh = whiF[(ks * 16 + nt) * 32 + lane];
        mma_f16(acc[nt], Ah.x, Ah.y, Ah.z, Ah.w, Bh.x, Bh.y);
        mma_f16(acc[nt], Al.x, Al.y, Al.z, Al.w, Bh.x, Bh.y);
      }
    }

    float as0 = 0.f, as8 = 0.f, ad0 = 0.f, ad8 = 0.f;
    __half* hrow0 = g_h + (size_t)((b * HH + ch) * NN + n0 + r0 + g) * DHH;
    __half* hrow8 = hrow0 + (size_t)8 * DHH;
#pragma unroll
    for (int nt = 0; nt < 16; ++nt) {
      int c = (nt << 3) + (tig << 1);
      float s0 = att_s[(ch << 7) + c], s1 = att_s[(ch << 7) + c + 1];
      float d0 = att_d[(ch << 7) + c], d1 = att_d[(ch << 7) + c + 1];
      as0 = fmaf(acc[nt][0], s0, fmaf(acc[nt][1], s1, as0));
      ad0 = fmaf(acc[nt][0], d0, fmaf(acc[nt][1], d1, ad0));
      as8 = fmaf(acc[nt][2], s0, fmaf(acc[nt][3], s1, as8));
      ad8 = fmaf(acc[nt][2], d0, fmaf(acc[nt][3], d1, ad8));
      *(__half2*)(hrow0 + c) = __half2(__float2half(acc[nt][0]), __float2half(acc[nt][1]));
      *(__half2*)(hrow8 + c) = __half2(__float2half(acc[nt][2]), __float2half(acc[nt][3]));
    }
#pragma unroll
    for (int off = 1; off <= 2; off <<= 1) {
      as0 += __shfl_xor_sync(0xffffffffu, as0, off);
      ad0 += __shfl_xor_sync(0xffffffffu, ad0, off);
      as8 += __shfl_xor_sync(0xffffffffu, as8, off);
      ad8 += __shfl_xor_sync(0xffffffffu, ad8, off);
    }
    if (tig == 0) {
      size_t base = (size_t)(b * HH + ch) * NN + n0 + r0 + g;
      g_as[base] = as0;
      g_ad[base] = ad0;
      g_as[base + 8] = as8;
      g_ad[base + 8] = ad8;
    }
  }
}

// ================= Kernel 2 (tensor-core): out = softmax-A @ h + b1 ==========
// block = (b,h). A entries (softmax weights, in [0,1]) built in registers as
// hi+lo fp16 pairs; B = h from smem via ldmatrix.x4.trans. No sorts/prefixes.
#define HS_PITCH 136                   // halves; 272 B rows -> conflict-free ldmatrix
#define T_HS   0                       // 256*136*2 = 69632
#define T_E1   69632
#define T_E2   (T_E1 + 1024)
#define T_ASV  (T_E2 + 1024)
#define T_ADV  (T_ASV + 1024)
#define T_F1   (T_ADV + 1024)
#define T_F2   (T_F1 + 1024)
#define T_BIAS (T_F2 + 1024)
#define K2_SMEM (T_BIAS + 512)

__global__ __launch_bounds__(256, 2) void k2_tc(const float* __restrict__ b1) {
  extern __shared__ char smem[];
  float* E1 = (float*)(smem + T_E1);
  float* E2 = (float*)(smem + T_E2);
  float* ASV = (float*)(smem + T_ASV);
  float* ADV = (float*)(smem + T_ADV);
  float* F1 = (float*)(smem + T_F1);
  float* F2 = (float*)(smem + T_F2);
  float* BIAS = (float*)(smem + T_BIAS);
  const uint32_t hs_addr = smem_u32g(smem) + T_HS;

  const int bh = blockIdx.x;
  const int h = bh & 3;
  const int b = bh >> 2;
  const int tid = threadIdx.x;
  const int wid = tid >> 5, lane = tid & 31;
  const int g = lane >> 2, tig = lane & 3;
  const __half* hb = g_h + (size_t)bh * NN * DHH;

  // ---- stage h tile: 256 rows x 16 cp16 each = 4096 units (NOT 4352!) ----
  for (int u = tid; u < 4096; u += 256) {
    int row = u >> 4, c = u & 15;
    cp16(hs_addr + (uint32_t)(row * 272 + c * 16), hb + (size_t)row * DHH + c * 8);
  }
  CP_COMMIT();

  // preamble: exps + per-row normalizers
  {
    float as = g_as[bh * NN + tid];
    float ad = g_ad[bh * NN + tid];
    ASV[tid] = as;
    ADV[tid] = ad;
    E1[tid] = __expf(as);
    E2[tid] = __expf(0.2f * as);
    if (tid < 128) BIAS[tid] = b1[(h << 7) + tid];
  }
  __syncthreads();
  {
    const float ad = ADV[tid];
    float SP = 0.f, SN = 0.f;
#pragma unroll 4
    for (int j = 0; j < NN; ++j) {
      float t = ad + ASV[j];
      if (t > 0.f) SP += E1[j]; else SN += E2[j];
    }
    const float f1 = __expf(ad), f2 = __expf(0.2f * ad);
    const float r = 1.0f / (f1 * SP + f2 * SN);
    F1[tid] = f1 * r;
    F2[tid] = f2 * r;
  }
  CP_WAIT(0);
  __syncthreads();

  // ---- main: warp = 32 rows (strip) x 64 d (job dj), 2 jobs per warp ----
  const int strip = wid;  // rows strip*32 .. +31
  float adA[2], adB[2], f1A[2], f2A[2], f1B[2], f2B[2];
#pragma unroll
  for (int mt = 0; mt < 2; ++mt) {
    int iA = strip * 32 + mt * 16 + g;
    adA[mt] = ADV[iA]; f1A[mt] = F1[iA]; f2A[mt] = F2[iA];
    adB[mt] = ADV[iA + 8]; f1B[mt] = F1[iA + 8]; f2B[mt] = F2[iA + 8];
  }
  const int matid = lane >> 3, mrow = lane & 7;

  for (int dj = 0; dj < 2; ++dj) {
    const int dbase = dj << 6;
    float acc[2][8][4];
#pragma unroll
    for (int mt = 0; mt < 2; ++mt)
#pragma unroll
      for (int nt = 0; nt < 8; ++nt)
#pragma unroll
        for (int q = 0; q < 4; ++q) acc[mt][nt][q] = 0.f;

#pragma unroll 2
    for (int kc = 0; kc < 16; ++kc) {
      const int jb = (kc << 4) + (tig << 1);
      float2 e1a = *(float2*)(E1 + jb), e1b = *(float2*)(E1 + jb + 8);
      float2 e2a = *(float2*)(E2 + jb), e2b = *(float2*)(E2 + jb + 8);
      float2 asa = *(float2*)(ASV + jb), asb = *(float2*)(ASV + jb + 8);

      uint32_t ahi[2][4], alo[2][4];
#pragma unroll
      for (int mt = 0; mt < 2; ++mt) {
        float vA0 = (asa.x + adA[mt] > 0.f) ? f1A[mt] * e1a.x : f2A[mt] * e2a.x;
        float vA1 = (asa.y + adA[mt] > 0.f) ? f1A[mt] * e1a.y : f2A[mt] * e2a.y;
        float vA2 = (asb.x + adA[mt] > 0.f) ? f1A[mt] * e1b.x : f2A[mt] * e2b.x;
        float vA3 = (asb.y + adA[mt] > 0.f) ? f1A[mt] * e1b.y : f2A[mt] * e2b.y;
        float vB0 = (asa.x + adB[mt] > 0.f) ? f1B[mt] * e1a.x : f2B[mt] * e2a.x;
        float vB1 = (asa.y + adB[mt] > 0.f) ? f1B[mt] * e1a.y : f2B[mt] * e2a.y;
        float vB2 = (asb.x + adB[mt] > 0.f) ? f1B[mt] * e1b.x : f2B[mt] * e2b.x;
        float vB3 = (asb.y + adB[mt] > 0.f) ? f1B[mt] * e1b.y : f2B[mt] * e2b.y;
        float hA0 = __half2float(__float2half(vA0)), hA1 = __half2float(__float2half(vA1));
        float hA2 = __half2float(__float2half(vA2)), hA3 = __half2float(__float2half(vA3));
        float hB0 = __half2float(__float2half(vB0)), hB1 = __half2float(__float2half(vB1));
        float hB2 = __half2float(__float2half(vB2)), hB3 = __half2float(__float2half(vB3));
        ahi[mt][0] = pack_f16(hA0, hA1);
        ahi[mt][1] = pack_f16(hB0, hB1);
        ahi[mt][2] = pack_f16(hA2, hA3);
        ahi[mt][3] = pack_f16(hB2, hB3);
        alo[mt][0] = pack_f16(vA0 - hA0, vA1 - hA1);
        alo[mt][1] = pack_f16(vB0 - hB0, vB1 - hB1);
        alo[mt][2] = pack_f16(vA2 - hA2, vA3 - hA3);
        alo[mt][3] = pack_f16(vB2 - hB2, vB3 - hB3);
      }

#pragma unroll
      for (int ntp = 0; ntp < 4; ++ntp) {
        uint32_t addr = hs_addr +
            (uint32_t)(((kc << 4) + ((matid & 1) << 3) + mrow) * 272 +
                       ((dbase + (ntp << 4) + ((matid >> 1) << 3)) << 1));
        uint32_t b0, b1r, b2, b3;
        ldm_x4t(b0, b1r, b2, b3, addr);
#pragma unroll
        for (int mt = 0; mt < 2; ++mt) {
          mma_f16(acc[mt][2 * ntp], ahi[mt][0], ahi[mt][1], ahi[mt][2], ahi[mt][3], b0, b1r);
          mma_f16(acc[mt][2 * ntp], alo[mt][0], alo[mt][1], alo[mt][2], alo[mt][3], b0, b1r);
          mma_f16(acc[mt][2 * ntp + 1], ahi[mt][0], ahi[mt][1], ahi[mt][2], ahi[mt][3], b2, b3);
          mma_f16(acc[mt][2 * ntp + 1], alo[mt][0], alo[mt][1], alo[mt][2], alo[mt][3], b2, b3);
        }
      }
    }

    // store y (+bias)
#pragma unroll
    for (int mt = 0; mt < 2; ++mt) {
      int iA = strip * 32 + mt * 16 + g;
      float* yrA = g_y + (size_t)(b * NN + iA) * HD + (h << 7);
      float* yrB = g_y + (size_t)(b * NN + iA + 8) * HD + (h << 7);
#pragma unroll
      for (int nt = 0; nt < 8; ++nt) {
        int d = dbase + (nt << 3) + (tig << 1);
        float b0v = BIAS[d], b1v = BIAS[d + 1];
        *(float2*)(yrA + d) = make_float2(acc[mt][nt][0] + b0v, acc[mt][nt][1] + b1v);
        *(float2*)(yrB + d) = make_float2(acc[mt][nt][2] + b0v, acc[mt][nt][3] + b1v);
      }
    }
  }
}

// ================= Kernel 3: LayerNorm + ELU + projection -> hp ===============
__global__ __launch_bounds__(256) void k3_ln(
    const float* __restrict__ gamma, const float* __restrict__ beta,
    const float* __restrict__ W2) {
  const int w = threadIdx.x >> 5, lane = threadIdx.x & 31;
  const int row = blockIdx.x * 8 + w;
  const float* yr = g_y + (size_t)row * HD;
  float4 v[4];
  float s = 0.f, sq = 0.f;
#pragma unroll
  for (int k = 0; k < 4; ++k) {
    v[k] = *(const float4*)(yr + (((k << 5) + lane) << 2));
    s += v[k].x + v[k].y + v[k].z + v[k].w;
    sq += v[k].x * v[k].x + v[k].y * v[k].y + v[k].z * v[k].z + v[k].w * v[k].w;
  }
#pragma unroll
  for (int off = 16; off > 0; off >>= 1) {
    s += __shfl_xor_sync(0xffffffffu, s, off);
    sq += __shfl_xor_sync(0xffffffffu, sq, off);
  }
  const float mu = s * (1.0f / 512.0f);
  const float var = sq * (1.0f / 512.0f) - mu * mu;
  const float rinv = rsqrtf(var + 1e-5f);
  float hp = 0.f;
#pragma unroll
  for (int k = 0; k < 4; ++k) {
    int c = (((k << 5) + lane) << 2);
    float4 g4 = *(const float4*)(gamma + c);
    float4 b4 = *(const float4*)(beta + c);
    float4 w4 = *(const float4*)(W2 + c);
    float t, e;
    t = (v[k].x - mu) * rinv * g4.x + b4.x; e = t > 0.f ? t : expm1f(t); hp = fmaf(e, w4.x, hp);
    t = (v[k].y - mu) * rinv * g4.y + b4.y; e = t > 0.f ? t : expm1f(t); hp = fmaf(e, w4.y, hp);
    t = (v[k].z - mu) * rinv * g4.z + b4.z; e = t > 0.f ? t : expm1f(t); hp = fmaf(e, w4.z, hp);
    t = (v[k].w - mu) * rinv * g4.w + b4.w; e = t > 0.f ? t : expm1f(t); hp = fmaf(e, w4.w, hp);
  }
#pragma unroll
  for (int off = 16; off > 0; off >>= 1) hp += __shfl_xor_sync(0xffffffffu, hp, off);
  if (lane == 0) g_hp[row] = hp;
}

// ================= Kernel 4: layer-2 scalar attention per batch ===============
__global__ __launch_bounds__(256) void k4_attn2(
    const float* __restrict__ att_src2, const float* __restrict__ att_dst2,
    const float* __restrict__ b2, float* __restrict__ out) {
  __shared__ float asv[NN], E1[NN], E2[NN], P1[NN], P2[NN];
  const int b = blockIdx.x, tid = threadIdx.x;
  const float v = g_hp[b * NN + tid];
  const float a_src = att_src2[0], a_dst = att_dst2[0];
  const float as = v * a_src;
  asv[tid] = as;
  const float e1 = __expf(as), e2 = __expf(0.2f * as);
  E1[tid] = e1; E2[tid] = e2; P1[tid] = e1 * v; P2[tid] = e2 * v;
  __syncthreads();
  const float ad = v * a_dst;
  float SP = 0.f, SN = 0.f, NP = 0.f, NNa = 0.f;
#pragma unroll 4
  for (int j = 0; j < NN; ++j) {
    float t = ad + asv[j];
    if (t > 0.f) { SP += E1[j]; NP += P1[j]; }
    else         { SN += E2[j]; NNa += P2[j]; }
  }
  const float f1 = __expf(ad), f2 = __expf(0.2f * ad);
  out[b * NN + tid] = (f1 * NP + f2 * NNa) / (f1 * SP + f2 * SN) + b2[0];
}

// ================================ launch ======================================
extern "C" void kernel_launch(void* const* d_in, const int* in_sizes, int n_in,
                              void* d_out, int out_size) {
  const float* x    = (const float*)d_in[0];
  const float* W1   = (const float*)d_in[2];
  const float* as1  = (const float*)d_in[3];
  const float* ad1  = (const float*)d_in[4];
  const float* b1   = (const float*)d_in[5];
  const float* gam  = (const float*)d_in[6];
  const float* bet  = (const float*)d_in[7];
  const float* W2   = (const float*)d_in[8];
  const float* as2  = (const float*)d_in[9];
  const float* ad2  = (const float*)d_in[10];
  const float* b2   = (const float*)d_in[11];
  float* out = (float*)d_out;

  cudaFuncSetAttribute(k1_mma, cudaFuncAttributeMaxDynamicSharedMemorySize, K1_SMEM);
  cudaFuncSetAttribute(k2_tc, cudaFuncAttributeMaxDynamicSharedMemorySize, K2_SMEM);

  k1_mma<<<512, 256, K1_SMEM>>>(x, W1, as1, ad1);
  k2_tc<<<BB * HH, 256, K2_SMEM>>>(b1);
  k3_ln<<<BB * NN / 8, 256>>>(gam, bet, W2);
  k4_attn2<<<BB, 256>>>(as2, ad2, b2, out);
}

// round 13
// speedup vs baseline: 1.7811x; 1.1125x over previous
#include <cuda_runtime.h>
#include <cuda_fp16.h>
#include <math.h>
#include <cstdint>

#define BB 256
#define NN 256
#define DIN 128
#define DHH 128
#define HH 4
#define HD 512

// ---------------- scratch (device globals; no allocation allowed) ----------------
__device__ __half g_h[(size_t)BB * HH * NN * DHH];  // [b][h][j][d] fp16
__device__ float g_as[BB * HH * NN];
__device__ float g_ad[BB * HH * NN];
__device__ __half g_y[(size_t)BB * NN * HD];        // [b][n][hd] fp16 (67 MB)
__device__ float g_hp[BB * NN];

// ===================== common helpers =====================
__device__ __forceinline__ void mma_f16(float* c, uint32_t a0, uint32_t a1, uint32_t a2,
                                        uint32_t a3, uint32_t b0, uint32_t b1) {
  asm volatile(
      "mma.sync.aligned.m16n8k16.row.col.f32.f16.f16.f32 "
      "{%0,%1,%2,%3}, {%4,%5,%6,%7}, {%8,%9}, {%0,%1,%2,%3};\n"
      : "+f"(c[0]), "+f"(c[1]), "+f"(c[2]), "+f"(c[3])
      : "r"(a0), "r"(a1), "r"(a2), "r"(a3), "r"(b0), "r"(b1));
}
__device__ __forceinline__ uint32_t pack_f16(float lo, float hi) {
  __half2 t(__float2half(lo), __float2half(hi));
  return *(uint32_t*)&t;
}
__device__ __forceinline__ uint32_t pack2rn(float lo, float hi) {
  __half2 t = __floats2half2_rn(lo, hi);
  return *(uint32_t*)&t;
}
__device__ __forceinline__ uint32_t smem_u32g(const void* p) {
  uint32_t a;
  asm("{ .reg .u64 t; cvta.to.shared.u64 t, %1; cvt.u32.u64 %0, t; }" : "=r"(a) : "l"(p));
  return a;
}
__device__ __forceinline__ void cp16(uint32_t dst, const void* src) {
  asm volatile("cp.async.cg.shared.global [%0], [%1], 16;" :: "r"(dst), "l"(src) : "memory");
}
#define CP_COMMIT() asm volatile("cp.async.commit_group;" ::: "memory")
#define CP_WAIT(n)  asm volatile("cp.async.wait_group %0;" :: "n"(n) : "memory")
__device__ __forceinline__ void ldm_x4t(uint32_t& r0, uint32_t& r1, uint32_t& r2, uint32_t& r3,
                                        uint32_t addr) {
  asm volatile("ldmatrix.sync.aligned.m8n8.x4.trans.shared.b16 {%0,%1,%2,%3}, [%4];"
               : "=r"(r0), "=r"(r1), "=r"(r2), "=r"(r3) : "r"(addr));
}

// ================= Kernel 1 (mma.sync fp16x2): h = x @ W1 + a_s/a_d ==========
#define SM_ATT 0
#define SM_AHI 4096
#define SM_ALO (SM_AHI + 32768)
#define SM_WHI (SM_ALO + 32768)
#define K1_SMEM (SM_WHI + 32768)

__global__ __launch_bounds__(256, 2) void k1_mma(
    const float* __restrict__ x, const float* __restrict__ W1,
    const float* __restrict__ att_src, const float* __restrict__ att_dst) {
  extern __shared__ char smem[];
  float* att = (float*)(smem + SM_ATT);
  const int tid = threadIdx.x;
  const int wid = tid >> 5, lane = tid & 31;
  const int g = lane >> 2, tig = lane & 3;
  const int bx = blockIdx.x;
  const int b = bx >> 1;
  const int n0 = (bx & 1) << 7;

  {
    att[tid] = att_src[tid];
    att[256 + tid] = att_src[256 + tid];
    att[512 + tid] = att_dst[tid];
    att[768 + tid] = att_dst[256 + tid];
  }

  {
    const float* xg = x + (size_t)(b * NN + n0) * DIN;
    char* ahi = smem + SM_AHI;
    char* alo = smem + SM_ALO;
#pragma unroll
    for (int it = 0; it < 16; ++it) {
      int idx = it * 256 + tid;
      int row = idx >> 5;
      int k4 = (idx & 31) << 2;
      float4 v = *(const float4*)(xg + row * DIN + k4);
      float hx = __half2float(__float2half(v.x));
      float hy = __half2float(__float2half(v.y));
      float hz = __half2float(__float2half(v.z));
      float hw = __half2float(__float2half(v.w));
      uint32_t wh0 = pack_f16(hx, hy), wh1 = pack_f16(hz, hw);
      uint32_t wl0 = pack_f16(v.x - hx, v.y - hy), wl1 = pack_f16(v.z - hz, v.w - hw);
      int aw = row >> 4;
      int ag = row & 7;
      int areg = ((row & 15) >= 8 ? 1 : 0) + ((k4 & 15) >= 8 ? 2 : 0);
      int ks = k4 >> 4;
      int atig = (k4 & 7) >> 1;
      int t0 = ag * 4 + atig;
      uint32_t byte0 = (uint32_t)(((aw * 8 + ks) * 32 + t0) * 16 + areg * 4);
      uint32_t byte1 = (uint32_t)(((aw * 8 + ks) * 32 + t0 + 1) * 16 + areg * 4);
      *(uint32_t*)(ahi + byte0) = wh0;
      *(uint32_t*)(ahi + byte1) = wh1;
      *(uint32_t*)(alo + byte0) = wl0;
      *(uint32_t*)(alo + byte1) = wl1;
    }
  }

  const float* att_s = att;
  const float* att_d = att + 512;
  const int r0 = wid << 4;

  for (int ch = 0; ch < HH; ++ch) {
    __syncthreads();
    {
      char* whi = smem + SM_WHI;
      const int d = tid & 127;
      const int kbase = (tid >> 7) << 6;
      const int nt = d >> 3, wg = d & 7;
#pragma unroll 8
      for (int kk = 0; kk < 32; ++kk) {
        int k = kbase + (kk << 1);
        float w0 = __ldg(W1 + (size_t)(k * HH + ch) * DHH + d);
        float w1 = __ldg(W1 + (size_t)((k + 1) * HH + ch) * DHH + d);
        int ks = k >> 4;
        int kkm = k & 15;
        int btig = (kkm & 7) >> 1;
        int breg = (kkm >= 8) ? 1 : 0;
        int t = wg * 4 + btig;
        uint32_t byte = (uint32_t)(((ks * 16 + nt) * 32 + t) * 8 + breg * 4);
        *(uint32_t*)(whi + byte) = pack_f16(w0, w1);
      }
    }
    __syncthreads();

    float acc[16][4];
#pragma unroll
    for (int nt = 0; nt < 16; ++nt)
#pragma unroll
      for (int q = 0; q < 4; ++q) acc[nt][q] = 0.f;

    const uint4* ahiF = (const uint4*)(smem + SM_AHI);
    const uint4* aloF = (const uint4*)(smem + SM_ALO);
    const uint2* whiF = (const uint2*)(smem + SM_WHI);

#pragma unroll
    for (int ks = 0; ks < 8; ++ks) {
      uint4 Ah = ahiF[(wid * 8 + ks) * 32 + lane];
      uint4 Al = aloF[(wid * 8 + ks) * 32 + lane];
#pragma unroll
      for (int nt = 0; nt < 16; ++nt) {
        uint2 Bh = whiF[(ks * 16 + nt) * 32 + lane];
        mma_f16(acc[nt], Ah.x, Ah.y, Ah.z, Ah.w, Bh.x, Bh.y);
        mma_f16(acc[nt], Al.x, Al.y, Al.z, Al.w, Bh.x, Bh.y);
      }
    }

    float as0 = 0.f, as8 = 0.f, ad0 = 0.f, ad8 = 0.f;
    __half* hrow0 = g_h + (size_t)((b * HH + ch) * NN + n0 + r0 + g) * DHH;
    __half* hrow8 = hrow0 + (size_t)8 * DHH;
#pragma unroll
    for (int nt = 0; nt < 16; ++nt) {
      int c = (nt << 3) + (tig << 1);
      float s0 = att_s[(ch << 7) + c], s1 = att_s[(ch << 7) + c + 1];
      float d0 = att_d[(ch << 7) + c], d1 = att_d[(ch << 7) + c + 1];
      as0 = fmaf(acc[nt][0], s0, fmaf(acc[nt][1], s1, as0));
      ad0 = fmaf(acc[nt][0], d0, fmaf(acc[nt][1], d1, ad0));
      as8 = fmaf(acc[nt][2], s0, fmaf(acc[nt][3], s1, as8));
      ad8 = fmaf(acc[nt][2], d0, fmaf(acc[nt][3], d1, ad8));
      *(__half2*)(hrow0 + c) = __half2(__float2half(acc[nt][0]), __float2half(acc[nt][1]));
      *(__half2*)(hrow8 + c) = __half2(__float2half(acc[nt][2]), __float2half(acc[nt][3]));
    }
#pragma unroll
    for (int off = 1; off <= 2; off <<= 1) {
      as0 += __shfl_xor_sync(0xffffffffu, as0, off);
      ad0 += __shfl_xor_sync(0xffffffffu, ad0, off);
      as8 += __shfl_xor_sync(0xffffffffu, as8, off);
      ad8 += __shfl_xor_sync(0xffffffffu, ad8, off);
    }
    if (tig == 0) {
      size_t base = (size_t)(b * HH + ch) * NN + n0 + r0 + g;
      g_as[base] = as0;
      g_ad[base] = ad0;
      g_as[base + 8] = as8;
      g_ad[base + 8] = ad8;
    }
  }
}

// ================= Kernel 2 (tensor-core): out = softmax-A @ h + b1 ==========
// A entries in [0,1] packed as single fp16 (no lo split); B via ldmatrix.x4.trans.
#define HS_PITCH 136
#define T_HS   0
#define T_E1   69632
#define T_E2   (T_E1 + 1024)
#define T_ASV  (T_E2 + 1024)
#define T_ADV  (T_ASV + 1024)
#define T_F1   (T_ADV + 1024)
#define T_F2   (T_F1 + 1024)
#define T_BIAS (T_F2 + 1024)
#define K2_SMEM (T_BIAS + 512)

__global__ __launch_bounds__(256, 2) void k2_tc(const float* __restrict__ b1) {
  extern __shared__ char smem[];
  float* E1 = (float*)(smem + T_E1);
  float* E2 = (float*)(smem + T_E2);
  float* ASV = (float*)(smem + T_ASV);
  float* ADV = (float*)(smem + T_ADV);
  float* F1 = (float*)(smem + T_F1);
  float* F2 = (float*)(smem + T_F2);
  float* BIAS = (float*)(smem + T_BIAS);
  const uint32_t hs_addr = smem_u32g(smem) + T_HS;

  const int bh = blockIdx.x;
  const int h = bh & 3;
  const int b = bh >> 2;
  const int tid = threadIdx.x;
  const int wid = tid >> 5, lane = tid & 31;
  const int g = lane >> 2, tig = lane & 3;
  const __half* hb = g_h + (size_t)bh * NN * DHH;

  // ---- stage h tile: 256 rows x 16 cp16 each = 4096 units ----
  for (int u = tid; u < 4096; u += 256) {
    int row = u >> 4, c = u & 15;
    cp16(hs_addr + (uint32_t)(row * 272 + c * 16), hb + (size_t)row * DHH + c * 8);
  }
  CP_COMMIT();

  {
    float as = g_as[bh * NN + tid];
    float ad = g_ad[bh * NN + tid];
    ASV[tid] = as;
    ADV[tid] = ad;
    E1[tid] = __expf(as);
    E2[tid] = __expf(0.2f * as);
    if (tid < 128) BIAS[tid] = b1[(h << 7) + tid];
  }
  __syncthreads();
  {
    const float ad = ADV[tid];
    float SP = 0.f, SN = 0.f;
#pragma unroll 4
    for (int j = 0; j < NN; ++j) {
      float t = ad + ASV[j];
      if (t > 0.f) SP += E1[j]; else SN += E2[j];
    }
    const float f1 = __expf(ad), f2 = __expf(0.2f * ad);
    const float r = 1.0f / (f1 * SP + f2 * SN);
    F1[tid] = f1 * r;
    F2[tid] = f2 * r;
  }
  CP_WAIT(0);
  __syncthreads();

  const int strip = wid;
  float adA[2], adB[2], f1A[2], f2A[2], f1B[2], f2B[2];
#pragma unroll
  for (int mt = 0; mt < 2; ++mt) {
    int iA = strip * 32 + mt * 16 + g;
    adA[mt] = ADV[iA]; f1A[mt] = F1[iA]; f2A[mt] = F2[iA];
    adB[mt] = ADV[iA + 8]; f1B[mt] = F1[iA + 8]; f2B[mt] = F2[iA + 8];
  }
  const int matid = lane >> 3, mrow = lane & 7;

  for (int dj = 0; dj < 2; ++dj) {
    const int dbase = dj << 6;
    float acc[2][8][4];
#pragma unroll
    for (int mt = 0; mt < 2; ++mt)
#pragma unroll
      for (int nt = 0; nt < 8; ++nt)
#pragma unroll
        for (int q = 0; q < 4; ++q) acc[mt][nt][q] = 0.f;

#pragma unroll 2
    for (int kc = 0; kc < 16; ++kc) {
      const int jb = (kc << 4) + (tig << 1);
      float2 e1a = *(float2*)(E1 + jb), e1b = *(float2*)(E1 + jb + 8);
      float2 e2a = *(float2*)(E2 + jb), e2b = *(float2*)(E2 + jb + 8);
      float2 asa = *(float2*)(ASV + jb), asb = *(float2*)(ASV + jb + 8);

      uint32_t afr[2][4];
#pragma unroll
      for (int mt = 0; mt < 2; ++mt) {
        float vA0 = (asa.x + adA[mt] > 0.f) ? f1A[mt] * e1a.x : f2A[mt] * e2a.x;
        float vA1 = (asa.y + adA[mt] > 0.f) ? f1A[mt] * e1a.y : f2A[mt] * e2a.y;
        float vA2 = (asb.x + adA[mt] > 0.f) ? f1A[mt] * e1b.x : f2A[mt] * e2b.x;
        float vA3 = (asb.y + adA[mt] > 0.f) ? f1A[mt] * e1b.y : f2A[mt] * e2b.y;
        float vB0 = (asa.x + adB[mt] > 0.f) ? f1B[mt] * e1a.x : f2B[mt] * e2a.x;
        float vB1 = (asa.y + adB[mt] > 0.f) ? f1B[mt] * e1a.y : f2B[mt] * e2a.y;
        float vB2 = (asb.x + adB[mt] > 0.f) ? f1B[mt] * e1b.x : f2B[mt] * e2b.x;
        float vB3 = (asb.y + adB[mt] > 0.f) ? f1B[mt] * e1b.y : f2B[mt] * e2b.y;
        afr[mt][0] = pack2rn(vA0, vA1);
        afr[mt][1] = pack2rn(vB0, vB1);
        afr[mt][2] = pack2rn(vA2, vA3);
        afr[mt][3] = pack2rn(vB2, vB3);
      }

#pragma unroll
      for (int ntp = 0; ntp < 4; ++ntp) {
        uint32_t addr = hs_addr +
            (uint32_t)(((kc << 4) + ((matid & 1) << 3) + mrow) * 272 +
                       ((dbase + (ntp << 4) + ((matid >> 1) << 3)) << 1));
        uint32_t b0, b1r, b2, b3;
        ldm_x4t(b0, b1r, b2, b3, addr);
#pragma unroll
        for (int mt = 0; mt < 2; ++mt) {
          mma_f16(acc[mt][2 * ntp], afr[mt][0], afr[mt][1], afr[mt][2], afr[mt][3], b0, b1r);
          mma_f16(acc[mt][2 * ntp + 1], afr[mt][0], afr[mt][1], afr[mt][2], afr[mt][3], b2, b3);
        }
      }
    }

    // store y (+bias) as fp16
#pragma unroll
    for (int mt = 0; mt < 2; ++mt) {
      int iA = strip * 32 + mt * 16 + g;
      __half* yrA = g_y + (size_t)(b * NN + iA) * HD + (h << 7);
      __half* yrB = g_y + (size_t)(b * NN + iA + 8) * HD + (h << 7);
#pragma unroll
      for (int nt = 0; nt < 8; ++nt) {
        int d = dbase + (nt << 3) + (tig << 1);
        float b0v = BIAS[d], b1v = BIAS[d + 1];
        *(__half2*)(yrA + d) = __floats2half2_rn(acc[mt][nt][0] + b0v, acc[mt][nt][1] + b1v);
        *(__half2*)(yrB + d) = __floats2half2_rn(acc[mt][nt][2] + b0v, acc[mt][nt][3] + b1v);
      }
    }
  }
}

// ================= Kernel 3: LayerNorm + ELU + projection -> hp (fp16 y) ======
__global__ __launch_bounds__(256) void k3_ln(
    const float* __restrict__ gamma, const float* __restrict__ beta,
    const float* __restrict__ W2) {
  const int w = threadIdx.x >> 5, lane = threadIdx.x & 31;
  const int row = blockIdx.x * 8 + w;
  const __half* yr = g_y + (size_t)row * HD;
  float vals[16];
  float s = 0.f, sq = 0.f;
#pragma unroll
  for (int k = 0; k < 2; ++k) {
    int c0 = ((k << 5) + lane) << 3;
    uint4 raw = *(const uint4*)(yr + c0);
    const __half2* h2 = (const __half2*)&raw;
#pragma unroll
    for (int j = 0; j < 4; ++j) {
      float2 f = __half22float2(h2[j]);
      vals[(k << 3) + (j << 1)] = f.x;
      vals[(k << 3) + (j << 1) + 1] = f.y;
      s += f.x + f.y;
      sq = fmaf(f.x, f.x, sq);
      sq = fmaf(f.y, f.y, sq);
    }
  }
#pragma unroll
  for (int off = 16; off > 0; off >>= 1) {
    s += __shfl_xor_sync(0xffffffffu, s, off);
    sq += __shfl_xor_sync(0xffffffffu, sq, off);
  }
  const float mu = s * (1.0f / 512.0f);
  const float var = sq * (1.0f / 512.0f) - mu * mu;
  const float rinv = rsqrtf(var + 1e-5f);
  float hp = 0.f;
#pragma unroll
  for (int k = 0; k < 2; ++k) {
    int c0 = ((k << 5) + lane) << 3;
#pragma unroll
    for (int q = 0; q < 2; ++q) {
      float4 g4 = *(const float4*)(gamma + c0 + (q << 2));
      float4 b4 = *(const float4*)(beta + c0 + (q << 2));
      float4 w4 = *(const float4*)(W2 + c0 + (q << 2));
      float* vv = vals + (k << 3) + (q << 2);
      float t, e;
      t = (vv[0] - mu) * rinv * g4.x + b4.x; e = t > 0.f ? t : expm1f(t); hp = fmaf(e, w4.x, hp);
      t = (vv[1] - mu) * rinv * g4.y + b4.y; e = t > 0.f ? t : expm1f(t); hp = fmaf(e, w4.y, hp);
      t = (vv[2] - mu) * rinv * g4.z + b4.z; e = t > 0.f ? t : expm1f(t); hp = fmaf(e, w4.z, hp);
      t = (vv[3] - mu) * rinv * g4.w + b4.w; e = t > 0.f ? t : expm1f(t); hp = fmaf(e, w4.w, hp);
    }
  }
#pragma unroll
  for (int off = 16; off > 0; off >>= 1) hp += __shfl_xor_sync(0xffffffffu, hp, off);
  if (lane == 0) g_hp[row] = hp;
}

// ================= Kernel 4: layer-2 scalar attention per batch ===============
__global__ __launch_bounds__(256) void k4_attn2(
    const float* __restrict__ att_src2, const float* __restrict__ att_dst2,
    const float* __restrict__ b2, float* __restrict__ out) {
  __shared__ float asv[NN], E1[NN], E2[NN], P1[NN], P2[NN];
  const int b = blockIdx.x, tid = threadIdx.x;
  const float v = g_hp[b * NN + tid];
  const float a_src = att_src2[0], a_dst = att_dst2[0];
  const float as = v * a_src;
  asv[tid] = as;
  const float e1 = __expf(as), e2 = __expf(0.2f * as);
  E1[tid] = e1; E2[tid] = e2; P1[tid] = e1 * v; P2[tid] = e2 * v;
  __syncthreads();
  const float ad = v * a_dst;
  float SP = 0.f, SN = 0.f, NP = 0.f, NNa = 0.f;
#pragma unroll 4
  for (int j = 0; j < NN; ++j) {
    float t = ad + asv[j];
    if (t > 0.f) { SP += E1[j]; NP += P1[j]; }
    else         { SN += E2[j]; NNa += P2[j]; }
  }
  const float f1 = __expf(ad), f2 = __expf(0.2f * ad);
  out[b * NN + tid] = (f1 * NP + f2 * NNa) / (f1 * SP + f2 * SN) + b2[0];
}

// ================================ launch ======================================
extern "C" void kernel_launch(void* const* d_in, const int* in_sizes, int n_in,
                              void* d_out, int out_size) {
  const float* x    = (const float*)d_in[0];
  const float* W1   = (const float*)d_in[2];
  const float* as1  = (const float*)d_in[3];
  const float* ad1  = (const float*)d_in[4];
  const float* b1   = (const float*)d_in[5];
  const float* gam  = (const float*)d_in[6];
  const float* bet  = (const float*)d_in[7];
  const float* W2   = (const float*)d_in[8];
  const float* as2  = (const float*)d_in[9];
  const float* ad2  = (const float*)d_in[10];
  const float* b2   = (const float*)d_in[11];
  float* out = (float*)d_out;

  cudaFuncSetAttribute(k1_mma, cudaFuncAttributeMaxDynamicSharedMemorySize, K1_SMEM);
  cudaFuncSetAttribute(k2_tc, cudaFuncAttributeMaxDynamicSharedMemorySize, K2_SMEM);

  k1_mma<<<512, 256, K1_SMEM>>>(x, W1, as1, ad1);
  k2_tc<<<BB * HH, 256, K2_SMEM>>>(b1);
  k3_ln<<<BB * NN / 8, 256>>>(gam, bet, W2);
  k4_attn2<<<BB, 256>>>(as2, ad2, b2, out);
}

// round 14
// speedup vs baseline: 1.8260x; 1.0252x over previous
#include <cuda_runtime.h>
#include <cuda_fp16.h>
#include <math.h>
#include <cstdint>

#define BB 256
#define NN 256
#define DIN 128
#define DHH 128
#define HH 4
#define HD 512

// ---------------- scratch (device globals; no allocation allowed) ----------------
__device__ __half g_h[(size_t)BB * HH * NN * DHH];  // [b][h][j][d] fp16
__device__ float g_as[BB * HH * NN];
__device__ float g_ad[BB * HH * NN];
__device__ __half g_y[(size_t)BB * NN * HD];        // [b][n][hd] fp16
__device__ float g_hp[BB * NN];

// ===================== common helpers =====================
__device__ __forceinline__ void mma_f16(float* c, uint32_t a0, uint32_t a1, uint32_t a2,
                                        uint32_t a3, uint32_t b0, uint32_t b1) {
  asm volatile(
      "mma.sync.aligned.m16n8k16.row.col.f32.f16.f16.f32 "
      "{%0,%1,%2,%3}, {%4,%5,%6,%7}, {%8,%9}, {%0,%1,%2,%3};\n"
      : "+f"(c[0]), "+f"(c[1]), "+f"(c[2]), "+f"(c[3])
      : "r"(a0), "r"(a1), "r"(a2), "r"(a3), "r"(b0), "r"(b1));
}
__device__ __forceinline__ uint32_t pack2rn(float lo, float hi) {
  __half2 t = __floats2half2_rn(lo, hi);
  return *(uint32_t*)&t;
}
__device__ __forceinline__ uint32_t smem_u32g(const void* p) {
  uint32_t a;
  asm("{ .reg .u64 t; cvta.to.shared.u64 t, %1; cvt.u32.u64 %0, t; }" : "=r"(a) : "l"(p));
  return a;
}
__device__ __forceinline__ void cp16(uint32_t dst, const void* src) {
  asm volatile("cp.async.cg.shared.global [%0], [%1], 16;" :: "r"(dst), "l"(src) : "memory");
}
#define CP_COMMIT() asm volatile("cp.async.commit_group;" ::: "memory")
#define CP_WAIT(n)  asm volatile("cp.async.wait_group %0;" :: "n"(n) : "memory")
__device__ __forceinline__ void ldm_x4t(uint32_t& r0, uint32_t& r1, uint32_t& r2, uint32_t& r3,
                                        uint32_t addr) {
  asm volatile("ldmatrix.sync.aligned.m8n8.x4.trans.shared.b16 {%0,%1,%2,%3}, [%4];"
               : "=r"(r0), "=r"(r1), "=r"(r2), "=r"(r3) : "r"(addr));
}

// ================= Kernel 1 (mma.sync fp16): h = x @ W1 + a_s/a_d =============
// Single fp16 MMA per (ks,nt) — x rounded to fp16 (error headroom measured in
// R13). smem: 68 KB -> 3 blocks/SM for this issue-bound kernel.
#define SM_ATT 0
#define SM_AHI 4096
#define SM_WHI (SM_AHI + 32768)
#define K1_SMEM (SM_WHI + 32768)

__global__ __launch_bounds__(256, 3) void k1_mma(
    const float* __restrict__ x, const float* __restrict__ W1,
    const float* __restrict__ att_src, const float* __restrict__ att_dst) {
  extern __shared__ char smem[];
  float* att = (float*)(smem + SM_ATT);
  const int tid = threadIdx.x;
  const int wid = tid >> 5, lane = tid & 31;
  const int g = lane >> 2, tig = lane & 3;
  const int bx = blockIdx.x;
  const int b = bx >> 1;
  const int n0 = (bx & 1) << 7;

  {
    att[tid] = att_src[tid];
    att[256 + tid] = att_src[256 + tid];
    att[512 + tid] = att_dst[tid];
    att[768 + tid] = att_dst[256 + tid];
  }

  // ---- stage A (x rows n0..n0+127) as fp16 fragments ----
  {
    const float* xg = x + (size_t)(b * NN + n0) * DIN;
    char* ahi = smem + SM_AHI;
#pragma unroll
    for (int it = 0; it < 16; ++it) {
      int idx = it * 256 + tid;
      int row = idx >> 5;
      int k4 = (idx & 31) << 2;
      float4 v = *(const float4*)(xg + row * DIN + k4);
      uint32_t wh0 = pack2rn(v.x, v.y), wh1 = pack2rn(v.z, v.w);
      int aw = row >> 4;
      int ag = row & 7;
      int areg = ((row & 15) >= 8 ? 1 : 0) + ((k4 & 15) >= 8 ? 2 : 0);
      int ks = k4 >> 4;
      int atig = (k4 & 7) >> 1;
      int t0 = ag * 4 + atig;
      uint32_t byte0 = (uint32_t)(((aw * 8 + ks) * 32 + t0) * 16 + areg * 4);
      uint32_t byte1 = (uint32_t)(((aw * 8 + ks) * 32 + t0 + 1) * 16 + areg * 4);
      *(uint32_t*)(ahi + byte0) = wh0;
      *(uint32_t*)(ahi + byte1) = wh1;
    }
  }

  const float* att_s = att;
  const float* att_d = att + 512;
  const int r0 = wid << 4;

  for (int ch = 0; ch < HH; ++ch) {
    __syncthreads();
    {
      char* whi = smem + SM_WHI;
      const int d = tid & 127;
      const int kbase = (tid >> 7) << 6;
      const int nt = d >> 3, wg = d & 7;
#pragma unroll 8
      for (int kk = 0; kk < 32; ++kk) {
        int k = kbase + (kk << 1);
        float w0 = __ldg(W1 + (size_t)(k * HH + ch) * DHH + d);
        float w1 = __ldg(W1 + (size_t)((k + 1) * HH + ch) * DHH + d);
        int ks = k >> 4;
        int kkm = k & 15;
        int btig = (kkm & 7) >> 1;
        int breg = (kkm >= 8) ? 1 : 0;
        int t = wg * 4 + btig;
        uint32_t byte = (uint32_t)(((ks * 16 + nt) * 32 + t) * 8 + breg * 4);
        *(uint32_t*)(whi + byte) = pack2rn(w0, w1);
      }
    }
    __syncthreads();

    float acc[16][4];
#pragma unroll
    for (int nt = 0; nt < 16; ++nt)
#pragma unroll
      for (int q = 0; q < 4; ++q) acc[nt][q] = 0.f;

    const uint4* ahiF = (const uint4*)(smem + SM_AHI);
    const uint2* whiF = (const uint2*)(smem + SM_WHI);

#pragma unroll
    for (int ks = 0; ks < 8; ++ks) {
      uint4 Ah = ahiF[(wid * 8 + ks) * 32 + lane];
#pragma unroll
      for (int nt = 0; nt < 16; ++nt) {
        uint2 Bh = whiF[(ks * 16 + nt) * 32 + lane];
        mma_f16(acc[nt], Ah.x, Ah.y, Ah.z, Ah.w, Bh.x, Bh.y);
      }
    }

    float as0 = 0.f, as8 = 0.f, ad0 = 0.f, ad8 = 0.f;
    __half* hrow0 = g_h + (size_t)((b * HH + ch) * NN + n0 + r0 + g) * DHH;
    __half* hrow8 = hrow0 + (size_t)8 * DHH;
#pragma unroll
    for (int nt = 0; nt < 16; ++nt) {
      int c = (nt << 3) + (tig << 1);
      float s0 = att_s[(ch << 7) + c], s1 = att_s[(ch << 7) + c + 1];
      float d0 = att_d[(ch << 7) + c], d1 = att_d[(ch << 7) + c + 1];
      as0 = fmaf(acc[nt][0], s0, fmaf(acc[nt][1], s1, as0));
      ad0 = fmaf(acc[nt][0], d0, fmaf(acc[nt][1], d1, ad0));
      as8 = fmaf(acc[nt][2], s0, fmaf(acc[nt][3], s1, as8));
      ad8 = fmaf(acc[nt][2], d0, fmaf(acc[nt][3], d1, ad8));
      *(__half2*)(hrow0 + c) = __floats2half2_rn(acc[nt][0], acc[nt][1]);
      *(__half2*)(hrow8 + c) = __floats2half2_rn(acc[nt][2], acc[nt][3]);
    }
#pragma unroll
    for (int off = 1; off <= 2; off <<= 1) {
      as0 += __shfl_xor_sync(0xffffffffu, as0, off);
      ad0 += __shfl_xor_sync(0xffffffffu, ad0, off);
      as8 += __shfl_xor_sync(0xffffffffu, as8, off);
      ad8 += __shfl_xor_sync(0xffffffffu, ad8, off);
    }
    if (tig == 0) {
      size_t base = (size_t)(b * HH + ch) * NN + n0 + r0 + g;
      g_as[base] = as0;
      g_ad[base] = ad0;
      g_as[base + 8] = as8;
      g_ad[base + 8] = ad8;
    }
  }
}

// ================= Kernel 2 (tensor-core): out = softmax-A @ h + b1 ==========
#define HS_PITCH 136
#define T_HS   0
#define T_E1   69632
#define T_E2   (T_E1 + 1024)
#define T_ASV  (T_E2 + 1024)
#define T_ADV  (T_ASV + 1024)
#define T_F1   (T_ADV + 1024)
#define T_F2   (T_F1 + 1024)
#define T_BIAS (T_F2 + 1024)
#define K2_SMEM (T_BIAS + 512)

__global__ __launch_bounds__(256, 2) void k2_tc(const float* __restrict__ b1) {
  extern __shared__ char smem[];
  float* E1 = (float*)(smem + T_E1);
  float* E2 = (float*)(smem + T_E2);
  float* ASV = (float*)(smem + T_ASV);
  float* ADV = (float*)(smem + T_ADV);
  float* F1 = (float*)(smem + T_F1);
  float* F2 = (float*)(smem + T_F2);
  float* BIAS = (float*)(smem + T_BIAS);
  const uint32_t hs_addr = smem_u32g(smem) + T_HS;

  const int bh = blockIdx.x;
  const int h = bh & 3;
  const int b = bh >> 2;
  const int tid = threadIdx.x;
  const int wid = tid >> 5, lane = tid & 31;
  const int g = lane >> 2, tig = lane & 3;
  const __half* hb = g_h + (size_t)bh * NN * DHH;

  for (int u = tid; u < 4096; u += 256) {
    int row = u >> 4, c = u & 15;
    cp16(hs_addr + (uint32_t)(row * 272 + c * 16), hb + (size_t)row * DHH + c * 8);
  }
  CP_COMMIT();

  {
    float as = g_as[bh * NN + tid];
    float ad = g_ad[bh * NN + tid];
    ASV[tid] = as;
    ADV[tid] = ad;
    E1[tid] = __expf(as);
    E2[tid] = __expf(0.2f * as);
    if (tid < 128) BIAS[tid] = b1[(h << 7) + tid];
  }
  __syncthreads();
  {
    const float ad = ADV[tid];
    float SP = 0.f, SN = 0.f;
#pragma unroll 4
    for (int j = 0; j < NN; ++j) {
      float t = ad + ASV[j];
      if (t > 0.f) SP += E1[j]; else SN += E2[j];
    }
    const float f1 = __expf(ad), f2 = __expf(0.2f * ad);
    const float r = 1.0f / (f1 * SP + f2 * SN);
    F1[tid] = f1 * r;
    F2[tid] = f2 * r;
  }
  CP_WAIT(0);
  __syncthreads();

  const int strip = wid;
  float adA[2], adB[2], f1A[2], f2A[2], f1B[2], f2B[2];
#pragma unroll
  for (int mt = 0; mt < 2; ++mt) {
    int iA = strip * 32 + mt * 16 + g;
    adA[mt] = ADV[iA]; f1A[mt] = F1[iA]; f2A[mt] = F2[iA];
    adB[mt] = ADV[iA + 8]; f1B[mt] = F1[iA + 8]; f2B[mt] = F2[iA + 8];
  }
  const int matid = lane >> 3, mrow = lane & 7;

  for (int dj = 0; dj < 2; ++dj) {
    const int dbase = dj << 6;
    float acc[2][8][4];
#pragma unroll
    for (int mt = 0; mt < 2; ++mt)
#pragma unroll
      for (int nt = 0; nt < 8; ++nt)
#pragma unroll
        for (int q = 0; q < 4; ++q) acc[mt][nt][q] = 0.f;

#pragma unroll 2
    for (int kc = 0; kc < 16; ++kc) {
      const int jb = (kc << 4) + (tig << 1);
      float2 e1a = *(float2*)(E1 + jb), e1b = *(float2*)(E1 + jb + 8);
      float2 e2a = *(float2*)(E2 + jb), e2b = *(float2*)(E2 + jb + 8);
      float2 asa = *(float2*)(ASV + jb), asb = *(float2*)(ASV + jb + 8);

      uint32_t afr[2][4];
#pragma unroll
      for (int mt = 0; mt < 2; ++mt) {
        float vA0 = (asa.x + adA[mt] > 0.f) ? f1A[mt] * e1a.x : f2A[mt] * e2a.x;
        float vA1 = (asa.y + adA[mt] > 0.f) ? f1A[mt] * e1a.y : f2A[mt] * e2a.y;
        float vA2 = (asb.x + adA[mt] > 0.f) ? f1A[mt] * e1b.x : f2A[mt] * e2b.x;
        float vA3 = (asb.y + adA[mt] > 0.f) ? f1A[mt] * e1b.y : f2A[mt] * e2b.y;
        float vB0 = (asa.x + adB[mt] > 0.f) ? f1B[mt] * e1a.x : f2B[mt] * e2a.x;
        float vB1 = (asa.y + adB[mt] > 0.f) ? f1B[mt] * e1a.y : f2B[mt] * e2a.y;
        float vB2 = (asb.x + adB[mt] > 0.f) ? f1B[mt] * e1b.x : f2B[mt] * e2b.x;
        float vB3 = (asb.y + adB[mt] > 0.f) ? f1B[mt] * e1b.y : f2B[mt] * e2b.y;
        afr[mt][0] = pack2rn(vA0, vA1);
        afr[mt][1] = pack2rn(vB0, vB1);
        afr[mt][2] = pack2rn(vA2, vA3);
        afr[mt][3] = pack2rn(vB2, vB3);
      }

#pragma unroll
      for (int ntp = 0; ntp < 4; ++ntp) {
        uint32_t addr = hs_addr +
            (uint32_t)(((kc << 4) + ((matid & 1) << 3) + mrow) * 272 +
                       ((dbase + (ntp << 4) + ((matid >> 1) << 3)) << 1));
        uint32_t b0, b1r, b2, b3;
        ldm_x4t(b0, b1r, b2, b3, addr);
#pragma unroll
        for (int mt = 0; mt < 2; ++mt) {
          mma_f16(acc[mt][2 * ntp], afr[mt][0], afr[mt][1], afr[mt][2], afr[mt][3], b0, b1r);
          mma_f16(acc[mt][2 * ntp + 1], afr[mt][0], afr[mt][1], afr[mt][2], afr[mt][3], b2, b3);
        }
      }
    }

#pragma unroll
    for (int mt = 0; mt < 2; ++mt) {
      int iA = strip * 32 + mt * 16 + g;
      __half* yrA = g_y + (size_t)(b * NN + iA) * HD + (h << 7);
      __half* yrB = g_y + (size_t)(b * NN + iA + 8) * HD + (h << 7);
#pragma unroll
      for (int nt = 0; nt < 8; ++nt) {
        int d = dbase + (nt << 3) + (tig << 1);
        float b0v = BIAS[d], b1v = BIAS[d + 1];
        *(__half2*)(yrA + d) = __floats2half2_rn(acc[mt][nt][0] + b0v, acc[mt][nt][1] + b1v);
        *(__half2*)(yrB + d) = __floats2half2_rn(acc[mt][nt][2] + b0v, acc[mt][nt][3] + b1v);
      }
    }
  }
}

// ================= Kernel 3: LayerNorm + ELU + projection -> hp (fp16 y) ======
__global__ __launch_bounds__(256) void k3_ln(
    const float* __restrict__ gamma, const float* __restrict__ beta,
    const float* __restrict__ W2) {
  const int w = threadIdx.x >> 5, lane = threadIdx.x & 31;
  const int row = blockIdx.x * 8 + w;
  const __half* yr = g_y + (size_t)row * HD;
  float vals[16];
  float s = 0.f, sq = 0.f;
#pragma unroll
  for (int k = 0; k < 2; ++k) {
    int c0 = ((k << 5) + lane) << 3;
    uint4 raw = *(const uint4*)(yr + c0);
    const __half2* h2 = (const __half2*)&raw;
#pragma unroll
    for (int j = 0; j < 4; ++j) {
      float2 f = __half22float2(h2[j]);
      vals[(k << 3) + (j << 1)] = f.x;
      vals[(k << 3) + (j << 1) + 1] = f.y;
      s += f.x + f.y;
      sq = fmaf(f.x, f.x, sq);
      sq = fmaf(f.y, f.y, sq);
    }
  }
#pragma unroll
  for (int off = 16; off > 0; off >>= 1) {
    s += __shfl_xor_sync(0xffffffffu, s, off);
    sq += __shfl_xor_sync(0xffffffffu, sq, off);
  }
  const float mu = s * (1.0f / 512.0f);
  const float var = sq * (1.0f / 512.0f) - mu * mu;
  const float rinv = rsqrtf(var + 1e-5f);
  float hp = 0.f;
#pragma unroll
  for (int k = 0; k < 2; ++k) {
    int c0 = ((k << 5) + lane) << 3;
#pragma unroll
    for (int q = 0; q < 2; ++q) {
      float4 g4 = *(const float4*)(gamma + c0 + (q << 2));
      float4 b4 = *(const float4*)(beta + c0 + (q << 2));
      float4 w4 = *(const float4*)(W2 + c0 + (q << 2));
      float* vv = vals + (k << 3) + (q << 2);
      float t, e;
      t = (vv[0] - mu) * rinv * g4.x + b4.x; e = t > 0.f ? t : expm1f(t); hp = fmaf(e, w4.x, hp);
      t = (vv[1] - mu) * rinv * g4.y + b4.y; e = t > 0.f ? t : expm1f(t); hp = fmaf(e, w4.y, hp);
      t = (vv[2] - mu) * rinv * g4.z + b4.z; e = t > 0.f ? t : expm1f(t); hp = fmaf(e, w4.z, hp);
      t = (vv[3] - mu) * rinv * g4.w + b4.w; e = t > 0.f ? t : expm1f(t); hp = fmaf(e, w4.w, hp);
    }
  }
#pragma unroll
  for (int off = 16; off > 0; off >>= 1) hp += __shfl_xor_sync(0xffffffffu, hp, off);
  if (lane == 0) g_hp[row] = hp;
}

// ================= Kernel 4: layer-2 scalar attention per batch ===============
__global__ __launch_bounds__(256) void k4_attn2(
    const float* __restrict__ att_src2, const float* __restrict__ att_dst2,
    const float* __restrict__ b2, float* __restrict__ out) {
  __shared__ float asv[NN], E1[NN], E2[NN], P1[NN], P2[NN];
  const int b = blockIdx.x, tid = threadIdx.x;
  const float v = g_hp[b * NN + tid];
  const float a_src = att_src2[0], a_dst = att_dst2[0];
  const float as = v * a_src;
  asv[tid] = as;
  const float e1 = __expf(as), e2 = __expf(0.2f * as);
  E1[tid] = e1; E2[tid] = e2; P1[tid] = e1 * v; P2[tid] = e2 * v;
  __syncthreads();
  const float ad = v * a_dst;
  float SP = 0.f, SN = 0.f, NP = 0.f, NNa = 0.f;
#pragma unroll 4
  for (int j = 0; j < NN; ++j) {
    float t = ad + asv[j];
    if (t > 0.f) { SP += E1[j]; NP += P1[j]; }
    else         { SN += E2[j]; NNa += P2[j]; }
  }
  const float f1 = __expf(ad), f2 = __expf(0.2f * ad);
  out[b * NN + tid] = (f1 * NP + f2 * NNa) / (f1 * SP + f2 * SN) + b2[0];
}

// ================================ launch ======================================
extern "C" void kernel_launch(void* const* d_in, const int* in_sizes, int n_in,
                              void* d_out, int out_size) {
  const float* x    = (const float*)d_in[0];
  const float* W1   = (const float*)d_in[2];
  const float* as1  = (const float*)d_in[3];
  const float* ad1  = (const float*)d_in[4];
  const float* b1   = (const float*)d_in[5];
  const float* gam  = (const float*)d_in[6];
  const float* bet  = (const float*)d_in[7];
  const float* W2   = (const float*)d_in[8];
  const float* as2  = (const float*)d_in[9];
  const float* ad2  = (const float*)d_in[10];
  const float* b2   = (const float*)d_in[11];
  float* out = (float*)d_out;

  cudaFuncSetAttribute(k1_mma, cudaFuncAttributeMaxDynamicSharedMemorySize, K1_SMEM);
  cudaFuncSetAttribute(k2_tc, cudaFuncAttributeMaxDynamicSharedMemorySize, K2_SMEM);

  k1_mma<<<512, 256, K1_SMEM>>>(x, W1, as1, ad1);
  k2_tc<<<BB * HH, 256, K2_SMEM>>>(b1);
  k3_ln<<<BB * NN / 8, 256>>>(gam, bet, W2);
  k4_attn2<<<BB, 256>>>(as2, ad2, b2, out);
}

// round 15
// speedup vs baseline: 2.1091x; 1.1550x over previous
#include <cuda_runtime.h>
#include <cuda_fp16.h>
#include <math.h>
#include <cstdint>

#define BB 256
#define NN 256
#define DIN 128
#define DHH 128
#define HH 4
#define HD 512

// ---------------- scratch (device globals; no allocation allowed) ----------------
__device__ __half g_h[(size_t)BB * HH * NN * DHH];  // [b][h][j][d] fp16
__device__ float g_as[BB * HH * NN];
__device__ float g_ad[BB * HH * NN];
__device__ __half g_y[(size_t)BB * NN * HD];        // [b][n][hd] fp16
__device__ float g_hp[BB * NN];
__device__ __half g_wfrag[4 * 16384];               // W1 fp16, mma-fragment order per chunk

// ===================== common helpers =====================
__device__ __forceinline__ void mma_f16(float* c, uint32_t a0, uint32_t a1, uint32_t a2,
                                        uint32_t a3, uint32_t b0, uint32_t b1) {
  asm volatile(
      "mma.sync.aligned.m16n8k16.row.col.f32.f16.f16.f32 "
      "{%0,%1,%2,%3}, {%4,%5,%6,%7}, {%8,%9}, {%0,%1,%2,%3};\n"
      : "+f"(c[0]), "+f"(c[1]), "+f"(c[2]), "+f"(c[3])
      : "r"(a0), "r"(a1), "r"(a2), "r"(a3), "r"(b0), "r"(b1));
}
__device__ __forceinline__ uint32_t pack2rn(float lo, float hi) {
  __half2 t = __floats2half2_rn(lo, hi);
  return *(uint32_t*)&t;
}
__device__ __forceinline__ uint32_t h2u(__half2 v) { return *(uint32_t*)&v; }
__device__ __forceinline__ uint32_t smem_u32g(const void* p) {
  uint32_t a;
  asm("{ .reg .u64 t; cvta.to.shared.u64 t, %1; cvt.u32.u64 %0, t; }" : "=r"(a) : "l"(p));
  return a;
}
__device__ __forceinline__ void cp16(uint32_t dst, const void* src) {
  asm volatile("cp.async.cg.shared.global [%0], [%1], 16;" :: "r"(dst), "l"(src) : "memory");
}
#define CP_COMMIT() asm volatile("cp.async.commit_group;" ::: "memory")
#define CP_WAIT(n)  asm volatile("cp.async.wait_group %0;" :: "n"(n) : "memory")
__device__ __forceinline__ void ldm_x4t(uint32_t& r0, uint32_t& r1, uint32_t& r2, uint32_t& r3,
                                        uint32_t addr) {
  asm volatile("ldmatrix.sync.aligned.m8n8.x4.trans.shared.b16 {%0,%1,%2,%3}, [%4];"
               : "=r"(r0), "=r"(r1), "=r"(r2), "=r"(r3) : "r"(addr));
}

// ================= Kernel 0: W1 -> fragment-ordered fp16 global ===============
__global__ __launch_bounds__(256) void k0_w(const float* __restrict__ W1) {
  int id = blockIdx.x * 256 + threadIdx.x;      // 32768 total
  int ch = id >> 13;
  int rest = id & 8191;
  int kp = rest >> 7;                           // 0..63
  int d = rest & 127;
  int k = kp << 1;
  float w0 = __ldg(W1 + (size_t)(k * HH + ch) * DHH + d);
  float w1 = __ldg(W1 + (size_t)((k + 1) * HH + ch) * DHH + d);
  int ks = k >> 4;
  int kkm = k & 15;
  int btig = (kkm & 7) >> 1;
  int breg = (kkm >= 8) ? 1 : 0;
  int nt = d >> 3, wg = d & 7;
  int t = wg * 4 + btig;
  uint32_t byte = (uint32_t)(((ks * 16 + nt) * 32 + t) * 8 + breg * 4);
  *(uint32_t*)((char*)g_wfrag + ch * 32768 + byte) = pack2rn(w0, w1);
}

// ================= Kernel 1: h = x @ W1 + a_s/a_d (cp.async W pipeline) =======
#define SM_ATT 0
#define SM_AHI 4096
#define SM_W0 (SM_AHI + 32768)
#define SM_W1B (SM_W0 + 32768)
#define K1_SMEM (SM_W1B + 32768)

__global__ __launch_bounds__(256, 2) void k1_mma(
    const float* __restrict__ x,
    const float* __restrict__ att_src, const float* __restrict__ att_dst) {
  extern __shared__ char smem[];
  float* att = (float*)(smem + SM_ATT);
  const uint32_t sb = smem_u32g(smem);
  const int tid = threadIdx.x;
  const int wid = tid >> 5, lane = tid & 31;
  const int g = lane >> 2, tig = lane & 3;
  const int bx = blockIdx.x;
  const int b = bx >> 1;
  const int n0 = (bx & 1) << 7;

  // issue W0 stream first (hidden under A staging)
  {
    const char* wsrc = (const char*)g_wfrag;
#pragma unroll
    for (int r = 0; r < 8; ++r) {
      int u = r * 256 + tid;
      cp16(sb + SM_W0 + (uint32_t)u * 16u, wsrc + u * 16);
    }
    CP_COMMIT();
  }

  {
    att[tid] = att_src[tid];
    att[256 + tid] = att_src[256 + tid];
    att[512 + tid] = att_dst[tid];
    att[768 + tid] = att_dst[256 + tid];
  }

  // ---- stage A (x rows n0..n0+127) as fp16 fragments ----
  {
    const float* xg = x + (size_t)(b * NN + n0) * DIN;
    char* ahi = smem + SM_AHI;
#pragma unroll
    for (int it = 0; it < 16; ++it) {
      int idx = it * 256 + tid;
      int row = idx >> 5;
      int k4 = (idx & 31) << 2;
      float4 v = *(const float4*)(xg + row * DIN + k4);
      uint32_t wh0 = pack2rn(v.x, v.y), wh1 = pack2rn(v.z, v.w);
      int aw = row >> 4;
      int ag = row & 7;
      int areg = ((row & 15) >= 8 ? 1 : 0) + ((k4 & 15) >= 8 ? 2 : 0);
      int ks = k4 >> 4;
      int atig = (k4 & 7) >> 1;
      int t0 = ag * 4 + atig;
      uint32_t byte0 = (uint32_t)(((aw * 8 + ks) * 32 + t0) * 16 + areg * 4);
      uint32_t byte1 = (uint32_t)(((aw * 8 + ks) * 32 + t0 + 1) * 16 + areg * 4);
      *(uint32_t*)(ahi + byte0) = wh0;
      *(uint32_t*)(ahi + byte1) = wh1;
    }
  }

  const float* att_s = att;
  const float* att_d = att + 512;
  const int r0 = wid << 4;

  for (int ch = 0; ch < HH; ++ch) {
    CP_WAIT(0);
    __syncthreads();     // W[ch] fully in buf ch&1; A visible (first iter)
    if (ch < 3) {        // stream W[ch+1] into the other buffer during mainloop
      uint32_t dst = sb + (((ch + 1) & 1) ? SM_W1B : SM_W0);
      const char* wsrc = (const char*)g_wfrag + (ch + 1) * 32768;
#pragma unroll
      for (int r = 0; r < 8; ++r) {
        int u = r * 256 + tid;
        cp16(dst + (uint32_t)u * 16u, wsrc + u * 16);
      }
      CP_COMMIT();
    }

    float acc[16][4];
#pragma unroll
    for (int nt = 0; nt < 16; ++nt)
#pragma unroll
      for (int q = 0; q < 4; ++q) acc[nt][q] = 0.f;

    const uint4* ahiF = (const uint4*)(smem + SM_AHI);
    const uint2* whiF = (const uint2*)(smem + ((ch & 1) ? SM_W1B : SM_W0));

#pragma unroll
    for (int ks = 0; ks < 8; ++ks) {
      uint4 Ah = ahiF[(wid * 8 + ks) * 32 + lane];
#pragma unroll
      for (int nt = 0; nt < 16; ++nt) {
        uint2 Bh = whiF[(ks * 16 + nt) * 32 + lane];
        mma_f16(acc[nt], Ah.x, Ah.y, Ah.z, Ah.w, Bh.x, Bh.y);
      }
    }

    float as0 = 0.f, as8 = 0.f, ad0 = 0.f, ad8 = 0.f;
    __half* hrow0 = g_h + (size_t)((b * HH + ch) * NN + n0 + r0 + g) * DHH;
    __half* hrow8 = hrow0 + (size_t)8 * DHH;
#pragma unroll
    for (int nt = 0; nt < 16; ++nt) {
      int c = (nt << 3) + (tig << 1);
      float s0 = att_s[(ch << 7) + c], s1 = att_s[(ch << 7) + c + 1];
      float d0 = att_d[(ch << 7) + c], d1 = att_d[(ch << 7) + c + 1];
      as0 = fmaf(acc[nt][0], s0, fmaf(acc[nt][1], s1, as0));
      ad0 = fmaf(acc[nt][0], d0, fmaf(acc[nt][1], d1, ad0));
      as8 = fmaf(acc[nt][2], s0, fmaf(acc[nt][3], s1, as8));
      ad8 = fmaf(acc[nt][2], d0, fmaf(acc[nt][3], d1, ad8));
      *(__half2*)(hrow0 + c) = __floats2half2_rn(acc[nt][0], acc[nt][1]);
      *(__half2*)(hrow8 + c) = __floats2half2_rn(acc[nt][2], acc[nt][3]);
    }
#pragma unroll
    for (int off = 1; off <= 2; off <<= 1) {
      as0 += __shfl_xor_sync(0xffffffffu, as0, off);
      ad0 += __shfl_xor_sync(0xffffffffu, ad0, off);
      as8 += __shfl_xor_sync(0xffffffffu, as8, off);
      ad8 += __shfl_xor_sync(0xffffffffu, ad8, off);
    }
    if (tig == 0) {
      size_t base = (size_t)(b * HH + ch) * NN + n0 + r0 + g;
      g_as[base] = as0;
      g_ad[base] = ad0;
      g_as[base + 8] = as8;
      g_ad[base + 8] = ad8;
    }
    __syncthreads();  // all reads of buf ch&1 done before it is restaged at ch+2
  }
}

// ================= Kernel 2 (tensor-core, half2 A-build) ======================
// Max-shifted factorization: m_i = lrelu(ad_i + M); F',E' in (0,1] -> fp16-safe.
#define T_HS   0
#define T_E1F  69632
#define T_E2F  (T_E1F + 1024)
#define T_ASV  (T_E2F + 1024)
#define T_ADV  (T_ASV + 1024)
#define T_F1   (T_ADV + 1024)
#define T_F2   (T_F1 + 1024)
#define T_BIAS (T_F2 + 1024)
#define T_E1H  (T_BIAS + 512)
#define T_E2H  (T_E1H + 512)
#define T_ASH  (T_E2H + 512)
#define T_RED  (T_ASH + 512)
#define K2_SMEM (T_RED + 64)

__global__ __launch_bounds__(256, 2) void k2_tc(const float* __restrict__ b1) {
  extern __shared__ char smem[];
  float* E1f = (float*)(smem + T_E1F);
  float* E2f = (float*)(smem + T_E2F);
  float* ASV = (float*)(smem + T_ASV);
  float* ADV = (float*)(smem + T_ADV);
  float* F1 = (float*)(smem + T_F1);
  float* F2 = (float*)(smem + T_F2);
  float* BIAS = (float*)(smem + T_BIAS);
  __half* E1H = (__half*)(smem + T_E1H);
  __half* E2H = (__half*)(smem + T_E2H);
  __half* ASH = (__half*)(smem + T_ASH);
  float* RED = (float*)(smem + T_RED);
  const uint32_t hs_addr = smem_u32g(smem) + T_HS;

  const int bh = blockIdx.x;
  const int h = bh & 3;
  const int b = bh >> 2;
  const int tid = threadIdx.x;
  const int wid = tid >> 5, lane = tid & 31;
  const int g = lane >> 2, tig = lane & 3;
  const __half* hb = g_h + (size_t)bh * NN * DHH;

  for (int u = tid; u < 4096; u += 256) {
    int row = u >> 4, c = u & 15;
    cp16(hs_addr + (uint32_t)(row * 272 + c * 16), hb + (size_t)row * DHH + c * 8);
  }
  CP_COMMIT();

  // preamble pass 1: load + block max of as
  const float as = g_as[bh * NN + tid];
  const float ad = g_ad[bh * NN + tid];
  ASV[tid] = as;
  ADV[tid] = ad;
  ASH[tid] = __float2half(as);
  if (tid < 128) BIAS[tid] = b1[(h << 7) + tid];
  {
    float mv = as;
#pragma unroll
    for (int off = 16; off > 0; off >>= 1) mv = fmaxf(mv, __shfl_xor_sync(0xffffffffu, mv, off));
    if (lane == 0) RED[wid] = mv;
  }
  __syncthreads();
  float M = RED[0];
#pragma unroll
  for (int q = 1; q < 8; ++q) M = fmaxf(M, RED[q]);

  // pass 2: shifted exps
  {
    float e1 = __expf(as - M);
    float e2 = __expf(0.2f * (as - M));
    E1f[tid] = e1; E2f[tid] = e2;
    E1H[tid] = __float2half(e1);
    E2H[tid] = __float2half(e2);
  }
  __syncthreads();

  // pass 3: per-row normalizers (exact fp32, shift cancels)
  {
    const float tM = ad + M;
    const float m = tM > 0.f ? tM : 0.2f * tM;
    const float F1p = __expf(tM - m);
    const float F2p = __expf(0.2f * tM - m);
    float SP = 0.f, SN = 0.f;
#pragma unroll 4
    for (int j = 0; j < NN; ++j) {
      float t = ad + ASV[j];
      if (t > 0.f) SP += E1f[j]; else SN += E2f[j];
    }
    const float r = 1.0f / (F1p * SP + F2p * SN);
    F1[tid] = F1p * r;
    F2[tid] = F2p * r;
  }
  CP_WAIT(0);
  __syncthreads();

  const int strip = wid;
  __half2 adA2[2], adB2[2], f1A2[2], f2A2[2], f1B2[2], f2B2[2];
#pragma unroll
  for (int mt = 0; mt < 2; ++mt) {
    int iA = strip * 32 + mt * 16 + g;
    adA2[mt] = __half2half2(__float2half(ADV[iA]));
    f1A2[mt] = __half2half2(__float2half(F1[iA]));
    f2A2[mt] = __half2half2(__float2half(F2[iA]));
    adB2[mt] = __half2half2(__float2half(ADV[iA + 8]));
    f1B2[mt] = __half2half2(__float2half(F1[iA + 8]));
    f2B2[mt] = __half2half2(__float2half(F2[iA + 8]));
  }
  const __half2 z2 = __half2half2(__float2half(0.f));
  const __half2* E1H2 = (const __half2*)E1H;
  const __half2* E2H2 = (const __half2*)E2H;
  const __half2* ASH2 = (const __half2*)ASH;
  const int matid = lane >> 3, mrow = lane & 7;

  for (int dj = 0; dj < 2; ++dj) {
    const int dbase = dj << 6;
    float acc[2][8][4];
#pragma unroll
    for (int mt = 0; mt < 2; ++mt)
#pragma unroll
      for (int nt = 0; nt < 8; ++nt)
#pragma unroll
        for (int q = 0; q < 4; ++q) acc[mt][nt][q] = 0.f;

#pragma unroll 2
    for (int kc = 0; kc < 16; ++kc) {
      const int jh = ((kc << 4) + (tig << 1)) >> 1;
      __half2 e1a = E1H2[jh], e1b = E1H2[jh + 4];
      __half2 e2a = E2H2[jh], e2b = E2H2[jh + 4];
      __half2 asa = ASH2[jh], asb = ASH2[jh + 4];

      uint32_t afr[2][4];
#pragma unroll
      for (int mt = 0; mt < 2; ++mt) {
        __half2 t, msk, p1, p2;
        t = __hadd2(asa, adA2[mt]); msk = __hgt2(t, z2);
        p1 = __hmul2(f1A2[mt], e1a); p2 = __hmul2(f2A2[mt], e2a);
        afr[mt][0] = h2u(__hfma2(msk, __hsub2(p1, p2), p2));
        t = __hadd2(asa, adB2[mt]); msk = __hgt2(t, z2);
        p1 = __hmul2(f1B2[mt], e1a); p2 = __hmul2(f2B2[mt], e2a);
        afr[mt][1] = h2u(__hfma2(msk, __hsub2(p1, p2), p2));
        t = __hadd2(asb, adA2[mt]); msk = __hgt2(t, z2);
        p1 = __hmul2(f1A2[mt], e1b); p2 = __hmul2(f2A2[mt], e2b);
        afr[mt][2] = h2u(__hfma2(msk, __hsub2(p1, p2), p2));
        t = __hadd2(asb, adB2[mt]); msk = __hgt2(t, z2);
        p1 = __hmul2(f1B2[mt], e1b); p2 = __hmul2(f2B2[mt], e2b);
        afr[mt][3] = h2u(__hfma2(msk, __hsub2(p1, p2), p2));
      }

#pragma unroll
      for (int ntp = 0; ntp < 4; ++ntp) {
        uint32_t addr = hs_addr +
            (uint32_t)(((kc << 4) + ((matid & 1) << 3) + mrow) * 272 +
                       ((dbase + (ntp << 4) + ((matid >> 1) << 3)) << 1));
        uint32_t b0, b1r, b2, b3;
        ldm_x4t(b0, b1r, b2, b3, addr);
#pragma unroll
        for (int mt = 0; mt < 2; ++mt) {
          mma_f16(acc[mt][2 * ntp], afr[mt][0], afr[mt][1], afr[mt][2], afr[mt][3], b0, b1r);
          mma_f16(acc[mt][2 * ntp + 1], afr[mt][0], afr[mt][1], afr[mt][2], afr[mt][3], b2, b3);
        }
      }
    }

#pragma unroll
    for (int mt = 0; mt < 2; ++mt) {
      int iA = strip * 32 + mt * 16 + g;
      __half* yrA = g_y + (size_t)(b * NN + iA) * HD + (h << 7);
      __half* yrB = g_y + (size_t)(b * NN + iA + 8) * HD + (h << 7);
#pragma unroll
      for (int nt = 0; nt < 8; ++nt) {
        int d = dbase + (nt << 3) + (tig << 1);
        float b0v = BIAS[d], b1v = BIAS[d + 1];
        *(__half2*)(yrA + d) = __floats2half2_rn(acc[mt][nt][0] + b0v, acc[mt][nt][1] + b1v);
        *(__half2*)(yrB + d) = __floats2half2_rn(acc[mt][nt][2] + b0v, acc[mt][nt][3] + b1v);
      }
    }
  }
}

// ================= Kernel 3: LayerNorm + ELU + projection -> hp (fp16 y) ======
__global__ __launch_bounds__(256) void k3_ln(
    const float* __restrict__ gamma, const float* __restrict__ beta,
    const float* __restrict__ W2) {
  const int w = threadIdx.x >> 5, lane = threadIdx.x & 31;
  const int row = blockIdx.x * 8 + w;
  const __half* yr = g_y + (size_t)row * HD;
  float vals[16];
  float s = 0.f, sq = 0.f;
#pragma unroll
  for (int k = 0; k < 2; ++k) {
    int c0 = ((k << 5) + lane) << 3;
    uint4 raw = *(const uint4*)(yr + c0);
    const __half2* h2 = (const __half2*)&raw;
#pragma unroll
    for (int j = 0; j < 4; ++j) {
      float2 f = __half22float2(h2[j]);
      vals[(k << 3) + (j << 1)] = f.x;
      vals[(k << 3) + (j << 1) + 1] = f.y;
      s += f.x + f.y;
      sq = fmaf(f.x, f.x, sq);
      sq = fmaf(f.y, f.y, sq);
    }
  }
#pragma unroll
  for (int off = 16; off > 0; off >>= 1) {
    s += __shfl_xor_sync(0xffffffffu, s, off);
    sq += __shfl_xor_sync(0xffffffffu, sq, off);
  }
  const float mu = s * (1.0f / 512.0f);
  const float var = sq * (1.0f / 512.0f) - mu * mu;
  const float rinv = rsqrtf(var + 1e-5f);
  float hp = 0.f;
#pragma unroll
  for (int k = 0; k < 2; ++k) {
    int c0 = ((k << 5) + lane) << 3;
#pragma unroll
    for (int q = 0; q < 2; ++q) {
      float4 g4 = *(const float4*)(gamma + c0 + (q << 2));
      float4 b4 = *(const float4*)(beta + c0 + (q << 2));
      float4 w4 = *(const float4*)(W2 + c0 + (q << 2));
      float* vv = vals + (k << 3) + (q << 2);
      float t, e;
      t = (vv[0] - mu) * rinv * g4.x + b4.x; e = t > 0.f ? t : expm1f(t); hp = fmaf(e, w4.x, hp);
      t = (vv[1] - mu) * rinv * g4.y + b4.y; e = t > 0.f ? t : expm1f(t); hp = fmaf(e, w4.y, hp);
      t = (vv[2] - mu) * rinv * g4.z + b4.z; e = t > 0.f ? t : expm1f(t); hp = fmaf(e, w4.z, hp);
      t = (vv[3] - mu) * rinv * g4.w + b4.w; e = t > 0.f ? t : expm1f(t); hp = fmaf(e, w4.w, hp);
    }
  }
#pragma unroll
  for (int off = 16; off > 0; off >>= 1) hp += __shfl_xor_sync(0xffffffffu, hp, off);
  if (lane == 0) g_hp[row] = hp;
}

// ================= Kernel 4: layer-2 scalar attention per batch ===============
__global__ __launch_bounds__(256) void k4_attn2(
    const float* __restrict__ att_src2, const float* __restrict__ att_dst2,
    const float* __restrict__ b2, float* __restrict__ out) {
  __shared__ float asv[NN], E1[NN], E2[NN], P1[NN], P2[NN];
  const int b = blockIdx.x, tid = threadIdx.x;
  const float v = g_hp[b * NN + tid];
  const float a_src = att_src2[0], a_dst = att_dst2[0];
  const float as = v * a_src;
  asv[tid] = as;
  const float e1 = __expf(as), e2 = __expf(0.2f * as);
  E1[tid] = e1; E2[tid] = e2; P1[tid] = e1 * v; P2[tid] = e2 * v;
  __syncthreads();
  const float ad = v * a_dst;
  float SP = 0.f, SN = 0.f, NP = 0.f, NNa = 0.f;
#pragma unroll 4
  for (int j = 0; j < NN; ++j) {
    float t = ad + asv[j];
    if (t > 0.f) { SP += E1[j]; NP += P1[j]; }
    else         { SN += E2[j]; NNa += P2[j]; }
  }
  const float f1 = __expf(ad), f2 = __expf(0.2f * ad);
  out[b * NN + tid] = (f1 * NP + f2 * NNa) / (f1 * SP + f2 * SN) + b2[0];
}

// ================================ launch ======================================
extern "C" void kernel_launch(void* const* d_in, const int* in_sizes, int n_in,
                              void* d_out, int out_size) {
  const float* x    = (const float*)d_in[0];
  const float* W1   = (const float*)d_in[2];
  const float* as1  = (const float*)d_in[3];
  const float* ad1  = (const float*)d_in[4];
  const float* b1   = (const float*)d_in[5];
  const float* gam  = (const float*)d_in[6];
  const float* bet  = (const float*)d_in[7];
  const float* W2   = (const float*)d_in[8];
  const float* as2  = (const float*)d_in[9];
  const float* ad2  = (const float*)d_in[10];
  const float* b2   = (const float*)d_in[11];
  float* out = (float*)d_out;

  cudaFuncSetAttribute(k1_mma, cudaFuncAttributeMaxDynamicSharedMemorySize, K1_SMEM);
  cudaFuncSetAttribute(k2_tc, cudaFuncAttributeMaxDynamicSharedMemorySize, K2_SMEM);

  k0_w<<<128, 256>>>(W1);
  k1_mma<<<512, 256, K1_SMEM>>>(x, as1, ad1);
  k2_tc<<<BB * HH, 256, K2_SMEM>>>(b1);
  k3_ln<<<BB * NN / 8, 256>>>(gam, bet, W2);
  k4_attn2<<<BB, 256>>>(as2, ad2, b2, out);
}

// round 17
// speedup vs baseline: 2.2893x; 1.0855x over previous
#include <cuda_runtime.h>
#include <cuda_fp16.h>
#include <math.h>
#include <cstdint>

#define BB 256
#define NN 256
#define DIN 128
#define DHH 128
#define HH 4
#define HD 512

// ---------------- scratch (device globals; no allocation allowed) ----------------
__device__ __half g_h[(size_t)BB * HH * NN * DHH];  // [b][h][j][d] fp16
__device__ float g_as[BB * HH * NN];
__device__ float g_ad[BB * HH * NN];
__device__ __half g_y[(size_t)BB * NN * HD];        // [b][n][hd] fp16
__device__ float g_hp[BB * NN];
__device__ __half g_wfrag[4 * 16384];               // W1 fp16, mma-fragment order per chunk

// ===================== common helpers =====================
__device__ __forceinline__ void mma_f16(float* c, uint32_t a0, uint32_t a1, uint32_t a2,
                                        uint32_t a3, uint32_t b0, uint32_t b1) {
  asm volatile(
      "mma.sync.aligned.m16n8k16.row.col.f32.f16.f16.f32 "
      "{%0,%1,%2,%3}, {%4,%5,%6,%7}, {%8,%9}, {%0,%1,%2,%3};\n"
      : "+f"(c[0]), "+f"(c[1]), "+f"(c[2]), "+f"(c[3])
      : "r"(a0), "r"(a1), "r"(a2), "r"(a3), "r"(b0), "r"(b1));
}
__device__ __forceinline__ uint32_t pack2rn(float lo, float hi) {
  __half2 t = __floats2half2_rn(lo, hi);
  return *(uint32_t*)&t;
}
__device__ __forceinline__ uint32_t h2u(__half2 v) { return *(uint32_t*)&v; }
__device__ __forceinline__ uint32_t smem_u32g(const void* p) {
  uint32_t a;
  asm("{ .reg .u64 t; cvta.to.shared.u64 t, %1; cvt.u32.u64 %0, t; }" : "=r"(a) : "l"(p));
  return a;
}
__device__ __forceinline__ void cp16(uint32_t dst, const void* src) {
  asm volatile("cp.async.cg.shared.global [%0], [%1], 16;" :: "r"(dst), "l"(src) : "memory");
}
#define CP_COMMIT() asm volatile("cp.async.commit_group;" ::: "memory")
#define CP_WAIT(n)  asm volatile("cp.async.wait_group %0;" :: "n"(n) : "memory")
__device__ __forceinline__ void ldm_x4t(uint32_t& r0, uint32_t& r1, uint32_t& r2, uint32_t& r3,
                                        uint32_t addr) {
  asm volatile("ldmatrix.sync.aligned.m8n8.x4.trans.shared.b16 {%0,%1,%2,%3}, [%4];"
               : "=r"(r0), "=r"(r1), "=r"(r2), "=r"(r3) : "r"(addr));
}

// ================= Kernel 0: W1 -> fragment-ordered fp16 global ===============
__global__ __launch_bounds__(256) void k0_w(const float* __restrict__ W1) {
  int id = blockIdx.x * 256 + threadIdx.x;      // 32768 total
  int ch = id >> 13;
  int rest = id & 8191;
  int kp = rest >> 7;                           // 0..63
  int d = rest & 127;
  int k = kp << 1;
  float w0 = __ldg(W1 + (size_t)(k * HH + ch) * DHH + d);
  float w1 = __ldg(W1 + (size_t)((k + 1) * HH + ch) * DHH + d);
  int ks = k >> 4;
  int kkm = k & 15;
  int btig = (kkm & 7) >> 1;
  int breg = (kkm >= 8) ? 1 : 0;
  int nt = d >> 3, wg = d & 7;
  int t = wg * 4 + btig;
  uint32_t byte = (uint32_t)(((ks * 16 + nt) * 32 + t) * 8 + breg * 4);
  *(uint32_t*)((char*)g_wfrag + ch * 32768 + byte) = pack2rn(w0, w1);
}

// ================= Kernel 1: h = x @ W1 + a_s/a_d (cp.async W pipeline) =======
#define SM_ATT 0
#define SM_AHI 4096
#define SM_W0 (SM_AHI + 32768)
#define SM_W1B (SM_W0 + 32768)
#define K1_SMEM (SM_W1B + 32768)

__global__ __launch_bounds__(256, 2) void k1_mma(
    const float* __restrict__ x,
    const float* __restrict__ att_src, const float* __restrict__ att_dst) {
  extern __shared__ char smem[];
  float* att = (float*)(smem + SM_ATT);
  const uint32_t sb = smem_u32g(smem);
  const int tid = threadIdx.x;
  const int wid = tid >> 5, lane = tid & 31;
  const int g = lane >> 2, tig = lane & 3;
  const int bx = blockIdx.x;
  const int b = bx >> 1;
  const int n0 = (bx & 1) << 7;

  {
    const char* wsrc = (const char*)g_wfrag;
#pragma unroll
    for (int r = 0; r < 8; ++r) {
      int u = r * 256 + tid;
      cp16(sb + SM_W0 + (uint32_t)u * 16u, wsrc + u * 16);
    }
    CP_COMMIT();
  }

  {
    att[tid] = att_src[tid];
    att[256 + tid] = att_src[256 + tid];
    att[512 + tid] = att_dst[tid];
    att[768 + tid] = att_dst[256 + tid];
  }

  {
    const float* xg = x + (size_t)(b * NN + n0) * DIN;
    char* ahi = smem + SM_AHI;
#pragma unroll
    for (int it = 0; it < 16; ++it) {
      int idx = it * 256 + tid;
      int row = idx >> 5;
      int k4 = (idx & 31) << 2;
      float4 v = *(const float4*)(xg + row * DIN + k4);
      uint32_t wh0 = pack2rn(v.x, v.y), wh1 = pack2rn(v.z, v.w);
      int aw = row >> 4;
      int ag = row & 7;
      int areg = ((row & 15) >= 8 ? 1 : 0) + ((k4 & 15) >= 8 ? 2 : 0);
      int ks = k4 >> 4;
      int atig = (k4 & 7) >> 1;
      int t0 = ag * 4 + atig;
      uint32_t byte0 = (uint32_t)(((aw * 8 + ks) * 32 + t0) * 16 + areg * 4);
      uint32_t byte1 = (uint32_t)(((aw * 8 + ks) * 32 + t0 + 1) * 16 + areg * 4);
      *(uint32_t*)(ahi + byte0) = wh0;
      *(uint32_t*)(ahi + byte1) = wh1;
    }
  }

  const float* att_s = att;
  const float* att_d = att + 512;
  const int r0 = wid << 4;

  for (int ch = 0; ch < HH; ++ch) {
    CP_WAIT(0);
    __syncthreads();
    if (ch < 3) {
      uint32_t dst = sb + (((ch + 1) & 1) ? SM_W1B : SM_W0);
      const char* wsrc = (const char*)g_wfrag + (ch + 1) * 32768;
#pragma unroll
      for (int r = 0; r < 8; ++r) {
        int u = r * 256 + tid;
        cp16(dst + (uint32_t)u * 16u, wsrc + u * 16);
      }
      CP_COMMIT();
    }

    float acc[16][4];
#pragma unroll
    for (int nt = 0; nt < 16; ++nt)
#pragma unroll
      for (int q = 0; q < 4; ++q) acc[nt][q] = 0.f;

    const uint4* ahiF = (const uint4*)(smem + SM_AHI);
    const uint2* whiF = (const uint2*)(smem + ((ch & 1) ? SM_W1B : SM_W0));

#pragma unroll
    for (int ks = 0; ks < 8; ++ks) {
      uint4 Ah = ahiF[(wid * 8 + ks) * 32 + lane];
#pragma unroll
      for (int nt = 0; nt < 16; ++nt) {
        uint2 Bh = whiF[(ks * 16 + nt) * 32 + lane];
        mma_f16(acc[nt], Ah.x, Ah.y, Ah.z, Ah.w, Bh.x, Bh.y);
      }
    }

    float as0 = 0.f, as8 = 0.f, ad0 = 0.f, ad8 = 0.f;
    __half* hrow0 = g_h + (size_t)((b * HH + ch) * NN + n0 + r0 + g) * DHH;
    __half* hrow8 = hrow0 + (size_t)8 * DHH;
#pragma unroll
    for (int nt = 0; nt < 16; ++nt) {
      int c = (nt << 3) + (tig << 1);
      float s0 = att_s[(ch << 7) + c], s1 = att_s[(ch << 7) + c + 1];
      float d0 = att_d[(ch << 7) + c], d1 = att_d[(ch << 7) + c + 1];
      as0 = fmaf(acc[nt][0], s0, fmaf(acc[nt][1], s1, as0));
      ad0 = fmaf(acc[nt][0], d0, fmaf(acc[nt][1], d1, ad0));
      as8 = fmaf(acc[nt][2], s0, fmaf(acc[nt][3], s1, as8));
      ad8 = fmaf(acc[nt][2], d0, fmaf(acc[nt][3], d1, ad8));
      *(__half2*)(hrow0 + c) = __floats2half2_rn(acc[nt][0], acc[nt][1]);
      *(__half2*)(hrow8 + c) = __floats2half2_rn(acc[nt][2], acc[nt][3]);
    }
#pragma unroll
    for (int off = 1; off <= 2; off <<= 1) {
      as0 += __shfl_xor_sync(0xffffffffu, as0, off);
      ad0 += __shfl_xor_sync(0xffffffffu, ad0, off);
      as8 += __shfl_xor_sync(0xffffffffu, as8, off);
      ad8 += __shfl_xor_sync(0xffffffffu, ad8, off);
    }
    if (tig == 0) {
      size_t base = (size_t)(b * HH + ch) * NN + n0 + r0 + g;
      g_as[base] = as0;
      g_ad[base] = ad0;
      g_as[base + 8] = as8;
      g_ad[base + 8] = ad8;
    }
    __syncthreads();
  }
}

// ================= Kernel 2 (tensor-core, half2 A-build) ======================
#define T_HS   0
#define T_E1F  69632
#define T_E2F  (T_E1F + 1024)
#define T_ASV  (T_E2F + 1024)
#define T_ADV  (T_ASV + 1024)
#define T_F1   (T_ADV + 1024)
#define T_F2   (T_F1 + 1024)
#define T_BIAS (T_F2 + 1024)
#define T_E1H  (T_BIAS + 512)
#define T_E2H  (T_E1H + 512)
#define T_ASH  (T_E2H + 512)
#define T_RED  (T_ASH + 512)
#define K2_SMEM (T_RED + 64)

__global__ __launch_bounds__(256, 2) void k2_tc(const float* __restrict__ b1) {
  extern __shared__ char smem[];
  float* E1f = (float*)(smem + T_E1F);
  float* E2f = (float*)(smem + T_E2F);
  float* ASV = (float*)(smem + T_ASV);
  float* ADV = (float*)(smem + T_ADV);
  float* F1 = (float*)(smem + T_F1);
  float* F2 = (float*)(smem + T_F2);
  float* BIAS = (float*)(smem + T_BIAS);
  __half* E1H = (__half*)(smem + T_E1H);
  __half* E2H = (__half*)(smem + T_E2H);
  __half* ASH = (__half*)(smem + T_ASH);
  float* RED = (float*)(smem + T_RED);
  const uint32_t hs_addr = smem_u32g(smem) + T_HS;

  const int bh = blockIdx.x;
  const int h = bh & 3;
  const int b = bh >> 2;
  const int tid = threadIdx.x;
  const int wid = tid >> 5, lane = tid & 31;
  const int g = lane >> 2, tig = lane & 3;
  const __half* hb = g_h + (size_t)bh * NN * DHH;

  for (int u = tid; u < 4096; u += 256) {
    int row = u >> 4, c = u & 15;
    cp16(hs_addr + (uint32_t)(row * 272 + c * 16), hb + (size_t)row * DHH + c * 8);
  }
  CP_COMMIT();

  const float as = g_as[bh * NN + tid];
  const float ad = g_ad[bh * NN + tid];
  ASV[tid] = as;
  ADV[tid] = ad;
  ASH[tid] = __float2half(as);
  if (tid < 128) BIAS[tid] = b1[(h << 7) + tid];
  {
    float mv = as;
#pragma unroll
    for (int off = 16; off > 0; off >>= 1) mv = fmaxf(mv, __shfl_xor_sync(0xffffffffu, mv, off));
    if (lane == 0) RED[wid] = mv;
  }
  __syncthreads();
  float M = RED[0];
#pragma unroll
  for (int q = 1; q < 8; ++q) M = fmaxf(M, RED[q]);

  {
    float e1 = __expf(as - M);
    float e2 = __expf(0.2f * (as - M));
    E1f[tid] = e1; E2f[tid] = e2;
    E1H[tid] = __float2half(e1);
    E2H[tid] = __float2half(e2);
  }
  __syncthreads();

  {
    const float tM = ad + M;
    const float m = tM > 0.f ? tM : 0.2f * tM;
    const float F1p = __expf(tM - m);
    const float F2p = __expf(0.2f * tM - m);
    float SP = 0.f, SN = 0.f;
#pragma unroll 4
    for (int j = 0; j < NN; ++j) {
      float t = ad + ASV[j];
      if (t > 0.f) SP += E1f[j]; else SN += E2f[j];
    }
    const float r = 1.0f / (F1p * SP + F2p * SN);
    F1[tid] = F1p * r;
    F2[tid] = F2p * r;
  }
  CP_WAIT(0);
  __syncthreads();

  const int strip = wid;
  __half2 adA2[2], adB2[2], f1A2[2], f2A2[2], f1B2[2], f2B2[2];
#pragma unroll
  for (int mt = 0; mt < 2; ++mt) {
    int iA = strip * 32 + mt * 16 + g;
    adA2[mt] = __half2half2(__float2half(ADV[iA]));
    f1A2[mt] = __half2half2(__float2half(F1[iA]));
    f2A2[mt] = __half2half2(__float2half(F2[iA]));
    adB2[mt] = __half2half2(__float2half(ADV[iA + 8]));
    f1B2[mt] = __half2half2(__float2half(F1[iA + 8]));
    f2B2[mt] = __half2half2(__float2half(F2[iA + 8]));
  }
  const __half2 z2 = __half2half2(__float2half(0.f));
  const __half2* E1H2 = (const __half2*)E1H;
  const __half2* E2H2 = (const __half2*)E2H;
  const __half2* ASH2 = (const __half2*)ASH;
  const int matid = lane >> 3, mrow = lane & 7;

  for (int dj = 0; dj < 2; ++dj) {
    const int dbase = dj << 6;
    float acc[2][8][4];
#pragma unroll
    for (int mt = 0; mt < 2; ++mt)
#pragma unroll
      for (int nt = 0; nt < 8; ++nt)
#pragma unroll
        for (int q = 0; q < 4; ++q) acc[mt][nt][q] = 0.f;

#pragma unroll 2
    for (int kc = 0; kc < 16; ++kc) {
      const int jh = ((kc << 4) + (tig << 1)) >> 1;
      __half2 e1a = E1H2[jh], e1b = E1H2[jh + 4];
      __half2 e2a = E2H2[jh], e2b = E2H2[jh + 4];
      __half2 asa = ASH2[jh], asb = ASH2[jh + 4];

      uint32_t afr[2][4];
#pragma unroll
      for (int mt = 0; mt < 2; ++mt) {
        __half2 t, msk, p1, p2;
        t = __hadd2(asa, adA2[mt]); msk = __hgt2(t, z2);
        p1 = __hmul2(f1A2[mt], e1a); p2 = __hmul2(f2A2[mt], e2a);
        afr[mt][0] = h2u(__hfma2(msk, __hsub2(p1, p2), p2));
        t = __hadd2(asa, adB2[mt]); msk = __hgt2(t, z2);
        p1 = __hmul2(f1B2[mt], e1a); p2 = __hmul2(f2B2[mt], e2a);
        afr[mt][1] = h2u(__hfma2(msk, __hsub2(p1, p2), p2));
        t = __hadd2(asb, adA2[mt]); msk = __hgt2(t, z2);
        p1 = __hmul2(f1A2[mt], e1b); p2 = __hmul2(f2A2[mt], e2b);
        afr[mt][2] = h2u(__hfma2(msk, __hsub2(p1, p2), p2));
        t = __hadd2(asb, adB2[mt]); msk = __hgt2(t, z2);
        p1 = __hmul2(f1B2[mt], e1b); p2 = __hmul2(f2B2[mt], e2b);
        afr[mt][3] = h2u(__hfma2(msk, __hsub2(p1, p2), p2));
      }

#pragma unroll
      for (int ntp = 0; ntp < 4; ++ntp) {
        uint32_t addr = hs_addr +
            (uint32_t)(((kc << 4) + ((matid & 1) << 3) + mrow) * 272 +
                       ((dbase + (ntp << 4) + ((matid >> 1) << 3)) << 1));
        uint32_t b0, b1r, b2, b3;
        ldm_x4t(b0, b1r, b2, b3, addr);
#pragma unroll
        for (int mt = 0; mt < 2; ++mt) {
          mma_f16(acc[mt][2 * ntp], afr[mt][0], afr[mt][1], afr[mt][2], afr[mt][3], b0, b1r);
          mma_f16(acc[mt][2 * ntp + 1], afr[mt][0], afr[mt][1], afr[mt][2], afr[mt][3], b2, b3);
        }
      }
    }

#pragma unroll
    for (int mt = 0; mt < 2; ++mt) {
      int iA = strip * 32 + mt * 16 + g;
      __half* yrA = g_y + (size_t)(b * NN + iA) * HD + (h << 7);
      __half* yrB = g_y + (size_t)(b * NN + iA + 8) * HD + (h << 7);
#pragma unroll
      for (int nt = 0; nt < 8; ++nt) {
        int d = dbase + (nt << 3) + (tig << 1);
        float b0v = BIAS[d], b1v = BIAS[d + 1];
        *(__half2*)(yrA + d) = __floats2half2_rn(acc[mt][nt][0] + b0v, acc[mt][nt][1] + b1v);
        *(__half2*)(yrB + d) = __floats2half2_rn(acc[mt][nt][2] + b0v, acc[mt][nt][3] + b1v);
      }
    }
  }
}

// ================= Kernel 3: LayerNorm + ELU + projection -> hp (lean) ========
__global__ __launch_bounds__(256) void k3_ln(
    const float* __restrict__ gamma, const float* __restrict__ beta,
    const float* __restrict__ W2) {
  const int w = threadIdx.x >> 5, lane = threadIdx.x & 31;
  const int row = blockIdx.x * 8 + w;
  const __half* yr = g_y + (size_t)row * HD;
  float vals[16];
  float s = 0.f, sq = 0.f;
#pragma unroll
  for (int k = 0; k < 2; ++k) {
    int c0 = ((k << 5) + lane) << 3;
    uint4 raw = *(const uint4*)(yr + c0);
    const __half2* h2 = (const __half2*)&raw;
#pragma unroll
    for (int j = 0; j < 4; ++j) {
      float2 f = __half22float2(h2[j]);
      vals[(k << 3) + (j << 1)] = f.x;
      vals[(k << 3) + (j << 1) + 1] = f.y;
      s += f.x + f.y;
      sq = fmaf(f.x, f.x, sq);
      sq = fmaf(f.y, f.y, sq);
    }
  }
#pragma unroll
  for (int off = 16; off > 0; off >>= 1) {
    s += __shfl_xor_sync(0xffffffffu, s, off);
    sq += __shfl_xor_sync(0xffffffffu, sq, off);
  }
  const float mu = s * (1.0f / 512.0f);
  const float var = sq * (1.0f / 512.0f) - mu * mu;
  const float rinv = rsqrtf(var + 1e-5f);
  const float nmur = -mu * rinv;   // z = fmaf(fmaf(v, rinv, nmur), g, b)
  float hp = 0.f;
#pragma unroll
  for (int k = 0; k < 2; ++k) {
    int c0 = ((k << 5) + lane) << 3;
#pragma unroll
    for (int q = 0; q < 2; ++q) {
      float4 g4 = *(const float4*)(gamma + c0 + (q << 2));
      float4 b4 = *(const float4*)(beta + c0 + (q << 2));
      float4 w4 = *(const float4*)(W2 + c0 + (q << 2));
      float* vv = vals + (k << 3) + (q << 2);
      float t, e;
      t = fmaf(fmaf(vv[0], rinv, nmur), g4.x, b4.x); e = t > 0.f ? t : (__expf(t) - 1.0f); hp = fmaf(e, w4.x, hp);
      t = fmaf(fmaf(vv[1], rinv, nmur), g4.y, b4.y); e = t > 0.f ? t : (__expf(t) - 1.0f); hp = fmaf(e, w4.y, hp);
      t = fmaf(fmaf(vv[2], rinv, nmur), g4.z, b4.z); e = t > 0.f ? t : (__expf(t) - 1.0f); hp = fmaf(e, w4.z, hp);
      t = fmaf(fmaf(vv[3], rinv, nmur), g4.w, b4.w); e = t > 0.f ? t : (__expf(t) - 1.0f); hp = fmaf(e, w4.w, hp);
    }
  }
#pragma unroll
  for (int off = 16; off > 0; off >>= 1) hp += __shfl_xor_sync(0xffffffffu, hp, off);
  if (lane == 0) g_hp[row] = hp;
}

// ================= Kernel 4: layer-2 scalar attention per batch ===============
__global__ __launch_bounds__(256) void k4_attn2(
    const float* __restrict__ att_src2, const float* __restrict__ att_dst2,
    const float* __restrict__ b2, float* __restrict__ out) {
  __shared__ float asv[NN], E1[NN], E2[NN], P1[NN], P2[NN];
  const int b = blockIdx.x, tid = threadIdx.x;
  const float v = g_hp[b * NN + tid];
  const float a_src = att_src2[0], a_dst = att_dst2[0];
  const float as = v * a_src;
  asv[tid] = as;
  const float e1 = __expf(as), e2 = __expf(0.2f * as);
  E1[tid] = e1; E2[tid] = e2; P1[tid] = e1 * v; P2[tid] = e2 * v;
  __syncthreads();
  const float ad = v * a_dst;
  float SPa = 0.f, SNa = 0.f, NPa = 0.f, NNa = 0.f;
  float SPb = 0.f, SNb = 0.f, NPb = 0.f, NNb = 0.f;
#pragma unroll 4
  for (int j = 0; j < NN; j += 2) {
    float t0 = ad + asv[j];
    float t1 = ad + asv[j + 1];
    if (t0 > 0.f) { SPa += E1[j]; NPa += P1[j]; }
    else          { SNa += E2[j]; NNa += P2[j]; }
    if (t1 > 0.f) { SPb += E1[j + 1]; NPb += P1[j + 1]; }
    else          { SNb += E2[j + 1]; NNb += P2[j + 1]; }
  }
  const float SP = SPa + SPb, SN = SNa + SNb, NP = NPa + NPb, NNs = NNa + NNb;
  const float f1 = __expf(ad), f2 = __expf(0.2f * ad);
  out[b * NN + tid] = (f1 * NP + f2 * NNs) / (f1 * SP + f2 * SN) + b2[0];
}

// ================================ launch ======================================
extern "C" void kernel_launch(void* const* d_in, const int* in_sizes, int n_in,
                              void* d_out, int out_size) {
  const float* x    = (const float*)d_in[0];
  const float* W1   = (const float*)d_in[2];
  const float* as1  = (const float*)d_in[3];
  const float* ad1  = (const float*)d_in[4];
  const float* b1   = (const float*)d_in[5];
  const float* gam  = (const float*)d_in[6];
  const float* bet  = (const float*)d_in[7];
  const float* W2   = (const float*)d_in[8];
  const float* as2  = (const float*)d_in[9];
  const float* ad2  = (const float*)d_in[10];
  const float* b2   = (const float*)d_in[11];
  float* out = (float*)d_out;

  cudaFuncSetAttribute(k1_mma, cudaFuncAttributeMaxDynamicSharedMemorySize, K1_SMEM);
  cudaFuncSetAttribute(k2_tc, cudaFuncAttributeMaxDynamicSharedMemorySize, K2_SMEM);

  k0_w<<<128, 256>>>(W1);
  k1_mma<<<512, 256, K1_SMEM>>>(x, as1, ad1);
  k2_tc<<<BB * HH, 256, K2_SMEM>>>(b1);
  k3_ln<<<BB * NN / 8, 256>>>(gam, bet, W2);
  k4_attn2<<<BB, 256>>>(as2, ad2, b2, out);
}